// round 1
// baseline (speedup 1.0000x reference)
#include <cuda_runtime.h>
#include <cstdint>

// Problem constants (fixed by the dataset)
#define NN   20000
#define EE   160000
#define FF   128
#define HID  128
#define NHEADS 4
#define GG   64
#define NCC  8
#define HC   512

// ---------------------------------------------------------------------------
// Scratch (device globals: allocation-free contract)
// ---------------------------------------------------------------------------
__device__ float g_agg [NN * HID];
__device__ float g_h   [NN * HID];   // after conv1
__device__ float g_h3  [NN * HID];   // after lin1
__device__ float g_h4  [NN * HID];   // after gconv l1
__device__ float g_h5  [NN * HID];   // after gconv l2
__device__ float g_skip[NN * HC];
__device__ float g_q   [NN * HC];
__device__ float g_k   [NN * HC];
__device__ float g_v   [NN * HC];
__device__ float g_attn[NN * HC];
__device__ float g_h2  [NN * HC];
__device__ float g_ex  [EE * NHEADS];   // logits, then exp values
__device__ float g_m   [NN * NHEADS];
__device__ float g_den [NN * NHEADS];
__device__ float g_pool[GG * HID];
__device__ float g_cnt [GG];

// ---------------------------------------------------------------------------
// Fused fp32 GEMM: C = op( A@W [+ A2@W2] [+ bias] [+ add1] [+ add2] )
// A: [Nrows, K] row-major, W: [K, M] row-major, C: [Nrows, M]
// BM=128, BN=64, BK=32, 256 threads, 8x4 microtile per thread
// ---------------------------------------------------------------------------
__global__ void __launch_bounds__(256)
gemm_fused(const float* __restrict__ A,  const float* __restrict__ W,
           const float* __restrict__ A2, const float* __restrict__ W2,
           const float* __restrict__ bias,
           const float* __restrict__ add1, const float* __restrict__ add2,
           float* __restrict__ C, int Nrows, int K, int M, int do_relu)
{
    __shared__ __align__(16) float As[32][132];  // [k][row], pad 132 keeps 16B align + few conflicts
    __shared__ __align__(16) float Ws[32][64];   // [k][col]

    const int tid  = threadIdx.x;
    const int tr   = tid >> 4;     // 0..15 -> rows tr*8 .. tr*8+7
    const int tc   = tid & 15;     // 0..15 -> cols tc*4 .. tc*4+3
    const int brow = blockIdx.x * 128;
    const int bcol = blockIdx.y * 64;

    float acc[8][4];
#pragma unroll
    for (int i = 0; i < 8; i++)
#pragma unroll
        for (int j = 0; j < 4; j++) acc[i][j] = 0.f;

    for (int pass = 0; pass < 2; ++pass) {
        const float* Ap = pass ? A2 : A;
        const float* Wp = pass ? W2 : W;
        if (!Ap) break;

        for (int k0 = 0; k0 < K; k0 += 32) {
            // A tile: 128 rows x 32 k, stored transposed As[k][row]
#pragma unroll
            for (int t = 0; t < 4; ++t) {
                int l   = tid + t * 256;    // float4 index, 0..1023
                int r   = l >> 3;           // tile row 0..127
                int kq  = (l & 7) * 4;      // k offset 0..28
                int grow = brow + r;
                float4 av = make_float4(0.f, 0.f, 0.f, 0.f);
                if (grow < Nrows)
                    av = *(const float4*)(Ap + (size_t)grow * K + k0 + kq);
                As[kq + 0][r] = av.x; As[kq + 1][r] = av.y;
                As[kq + 2][r] = av.z; As[kq + 3][r] = av.w;
            }
            // W tile: 32 k x 64 cols
#pragma unroll
            for (int t = 0; t < 2; ++t) {
                int l  = tid + t * 256;     // 0..511
                int r  = l >> 4;            // k 0..31
                int cq = (l & 15) * 4;      // col 0..60
                *(float4*)&Ws[r][cq] =
                    *(const float4*)(Wp + (size_t)(k0 + r) * M + bcol + cq);
            }
            __syncthreads();

#pragma unroll
            for (int kk = 0; kk < 32; ++kk) {
                float4 a0 = *(const float4*)&As[kk][tr * 8];
                float4 a1 = *(const float4*)&As[kk][tr * 8 + 4];
                float4 b  = *(const float4*)&Ws[kk][tc * 4];
                float aa[8] = {a0.x, a0.y, a0.z, a0.w, a1.x, a1.y, a1.z, a1.w};
                float bb[4] = {b.x, b.y, b.z, b.w};
#pragma unroll
                for (int i = 0; i < 8; i++)
#pragma unroll
                    for (int j = 0; j < 4; j++)
                        acc[i][j] += aa[i] * bb[j];
            }
            __syncthreads();
        }
    }

#pragma unroll
    for (int i = 0; i < 8; i++) {
        int row = brow + tr * 8 + i;
        if (row >= Nrows) continue;
#pragma unroll
        for (int j = 0; j < 4; j++) {
            int col = bcol + tc * 4 + j;
            float v = acc[i][j];
            if (bias) v += bias[col];
            size_t o = (size_t)row * M + col;
            if (add1) v += add1[o];
            if (add2) v += add2[o];
            if (do_relu) v = fmaxf(v, 0.f);
            C[o] = v;
        }
    }
}

// ---------------------------------------------------------------------------
// Edge scatter-add for GraphConv aggregation: agg[dst] += in[src]  (128 cols)
// One thread per (edge, 4-col group), float4 gather + 4 atomics (REDG)
// ---------------------------------------------------------------------------
__global__ void scatter_add128(const float* __restrict__ in,
                               const int* __restrict__ src,
                               const int* __restrict__ dst,
                               float* __restrict__ agg)
{
    long idx = (long)blockIdx.x * blockDim.x + threadIdx.x;
    if (idx >= (long)EE * 32) return;
    int e  = (int)(idx >> 5);
    int c  = ((int)idx & 31) * 4;
    int s  = src[e], d = dst[e];
    float4 v = *(const float4*)(in + (size_t)s * HID + c);
    float* p = agg + (size_t)d * HID + c;
    atomicAdd(p + 0, v.x);
    atomicAdd(p + 1, v.y);
    atomicAdd(p + 2, v.z);
    atomicAdd(p + 3, v.w);
}

// ---------------------------------------------------------------------------
// Attention
// ---------------------------------------------------------------------------
__device__ __forceinline__ void atomicMaxFloat(float* addr, float val)
{
    int* ia = (int*)addr;
    int old = __float_as_int(*addr);
    while (val > __int_as_float(old)) {
        int assumed = old;
        old = atomicCAS(ia, assumed, __float_as_int(val));
        if (old == assumed) break;
    }
}

__global__ void fill_neg_inf(float* __restrict__ p, int n)
{
    int i = blockIdx.x * blockDim.x + threadIdx.x;
    if (i < n) p[i] = __int_as_float(0xff800000);  // -inf
}

// block = 128 threads = 4 warps; one block per edge; warp w -> head w
__global__ void edge_logits_max(const float* __restrict__ q,
                                const float* __restrict__ k,
                                const int* __restrict__ src,
                                const int* __restrict__ dst,
                                float* __restrict__ lg,
                                float* __restrict__ m)
{
    int e    = blockIdx.x;
    int h    = threadIdx.x >> 5;
    int lane = threadIdx.x & 31;
    int d = dst[e], s = src[e];
    float4 qa = *((const float4*)(q + (size_t)d * HC + h * HID) + lane);
    float4 ka = *((const float4*)(k + (size_t)s * HC + h * HID) + lane);
    float sum = qa.x * ka.x + qa.y * ka.y + qa.z * ka.z + qa.w * ka.w;
#pragma unroll
    for (int o = 16; o; o >>= 1) sum += __shfl_xor_sync(0xffffffffu, sum, o);
    if (lane == 0) {
        sum *= 0.08838834764831843f;   // 1/sqrt(128)
        lg[e * NHEADS + h] = sum;
        atomicMaxFloat(&m[d * NHEADS + h], sum);
    }
}

__global__ void exp_den(const int* __restrict__ dst,
                        float* __restrict__ lg,       // in: logits, out: exp
                        const float* __restrict__ m,
                        float* __restrict__ den)
{
    int i = blockIdx.x * blockDim.x + threadIdx.x;
    if (i >= EE * NHEADS) return;
    int e = i >> 2, h = i & 3;
    int d = dst[e];
    float ex = expf(lg[i] - m[d * NHEADS + h]);
    lg[i] = ex;
    atomicAdd(&den[d * NHEADS + h], ex);
}

// attn[dst] += alpha * v[src]; one thread per (edge, 4-col group) over HC=512
__global__ void alpha_v_scatter(const float* __restrict__ v,
                                const int* __restrict__ src,
                                const int* __restrict__ dst,
                                const float* __restrict__ ex,
                                const float* __restrict__ den,
                                float* __restrict__ attn)
{
    long idx = (long)blockIdx.x * blockDim.x + threadIdx.x;
    if (idx >= (long)EE * 128) return;
    int e = (int)(idx >> 7);
    int c = ((int)idx & 127) * 4;     // 0..508
    int h = c >> 7;                   // head
    int s = src[e], d = dst[e];
    float alpha = ex[e * NHEADS + h] / (den[d * NHEADS + h] + 1e-16f);
    float4 vv = *(const float4*)(v + (size_t)s * HC + c);
    float* p = attn + (size_t)d * HC + c;
    atomicAdd(p + 0, alpha * vv.x);
    atomicAdd(p + 1, alpha * vv.y);
    atomicAdd(p + 2, alpha * vv.z);
    atomicAdd(p + 3, alpha * vv.w);
}

// ---------------------------------------------------------------------------
// Pooling + final FC
// ---------------------------------------------------------------------------
__global__ void pool_accum(const float* __restrict__ h,
                           const int* __restrict__ batch,
                           float* __restrict__ pool, float* __restrict__ cnt)
{
    int idx = blockIdx.x * blockDim.x + threadIdx.x;
    if (idx >= NN * HID) return;
    int i = idx >> 7, c = idx & 127;
    int b = batch[i];
    atomicAdd(&pool[b * HID + c], h[idx]);
    if (c == 0) atomicAdd(&cnt[b], 1.0f);
}

__global__ void pool_fc(const float* __restrict__ pool,
                        const float* __restrict__ cnt,
                        const float* __restrict__ fcW,
                        const float* __restrict__ fcb,
                        float* __restrict__ out)
{
    int g = blockIdx.x;       // 0..63
    int c = threadIdx.x;      // 0..7
    float inv = 1.f / fmaxf(cnt[g], 1.f);
    float s = 0.f;
    for (int k = 0; k < HID; k++)
        s += pool[g * HID + k] * fcW[k * NCC + c];
    out[g * NCC + c] = s * inv + fcb[c];
}

// ---------------------------------------------------------------------------
// Launch
// ---------------------------------------------------------------------------
extern "C" void kernel_launch(void* const* d_in, const int* in_sizes, int n_in,
                              void* d_out, int out_size)
{
    const float* x        = (const float*)d_in[0];
    const int*   ei       = (const int*)  d_in[1];
    const int*   src      = ei;
    const int*   dst      = ei + EE;
    const int*   batch    = (const int*)  d_in[2];
    const float* c1_Wr    = (const float*)d_in[3];
    const float* c1_br    = (const float*)d_in[4];
    const float* c1_Wroot = (const float*)d_in[5];
    const float* tq_W  = (const float*)d_in[6];  const float* tq_b  = (const float*)d_in[7];
    const float* tk_W  = (const float*)d_in[8];  const float* tk_b  = (const float*)d_in[9];
    const float* tv_W  = (const float*)d_in[10]; const float* tv_b  = (const float*)d_in[11];
    const float* ts_W  = (const float*)d_in[12]; const float* ts_b  = (const float*)d_in[13];
    const float* skip_W = (const float*)d_in[14];
    const float* l1W    = (const float*)d_in[15]; const float* l1b = (const float*)d_in[16];
    const float* g1_Wr = (const float*)d_in[17]; const float* g1_br = (const float*)d_in[18];
    const float* g1_Wroot = (const float*)d_in[19];
    const float* g2_Wr = (const float*)d_in[20]; const float* g2_br = (const float*)d_in[21];
    const float* g2_Wroot = (const float*)d_in[22];
    const float* fc_W = (const float*)d_in[23]; const float* fc_b = (const float*)d_in[24];
    float* out = (float*)d_out;

    float *agg, *h, *h3, *h4, *h5, *skip, *q, *k, *v, *attn, *h2, *ex, *m, *den, *pool, *cnt;
    cudaGetSymbolAddress((void**)&agg,  g_agg);
    cudaGetSymbolAddress((void**)&h,    g_h);
    cudaGetSymbolAddress((void**)&h3,   g_h3);
    cudaGetSymbolAddress((void**)&h4,   g_h4);
    cudaGetSymbolAddress((void**)&h5,   g_h5);
    cudaGetSymbolAddress((void**)&skip, g_skip);
    cudaGetSymbolAddress((void**)&q,    g_q);
    cudaGetSymbolAddress((void**)&k,    g_k);
    cudaGetSymbolAddress((void**)&v,    g_v);
    cudaGetSymbolAddress((void**)&attn, g_attn);
    cudaGetSymbolAddress((void**)&h2,   g_h2);
    cudaGetSymbolAddress((void**)&ex,   g_ex);
    cudaGetSymbolAddress((void**)&m,    g_m);
    cudaGetSymbolAddress((void**)&den,  g_den);
    cudaGetSymbolAddress((void**)&pool, g_pool);
    cudaGetSymbolAddress((void**)&cnt,  g_cnt);

    const dim3 gemm_block(256);
    const dim3 grid128((NN + 127) / 128, HID / 64);   // M=128
    const dim3 grid512((NN + 127) / 128, HC  / 64);   // M=512
    const int SC_GRID = (EE * 32 + 255) / 256;        // scatter_add128
    const int AV_GRID = (EE * 128 + 255) / 256;       // alpha_v

    // --- conv1: h = relu( (scatter x) @ Wr + br + x @ Wroot )
    cudaMemsetAsync(agg, 0, (size_t)NN * HID * sizeof(float));
    scatter_add128<<<SC_GRID, 256>>>(x, src, dst, agg);
    gemm_fused<<<grid128, gemm_block>>>(agg, c1_Wr, x, c1_Wroot, c1_br,
                                        nullptr, nullptr, h, NN, 128, 128, 1);

    // --- projections off h
    gemm_fused<<<grid512, gemm_block>>>(h, skip_W, nullptr, nullptr, nullptr,
                                        nullptr, nullptr, skip, NN, 128, 512, 0);
    gemm_fused<<<grid512, gemm_block>>>(h, tq_W, nullptr, nullptr, tq_b,
                                        nullptr, nullptr, q, NN, 128, 512, 0);
    gemm_fused<<<grid512, gemm_block>>>(h, tk_W, nullptr, nullptr, tk_b,
                                        nullptr, nullptr, k, NN, 128, 512, 0);
    gemm_fused<<<grid512, gemm_block>>>(h, tv_W, nullptr, nullptr, tv_b,
                                        nullptr, nullptr, v, NN, 128, 512, 0);

    // --- edge softmax attention
    fill_neg_inf<<<(NN * NHEADS + 255) / 256, 256>>>(m, NN * NHEADS);
    cudaMemsetAsync(den,  0, (size_t)NN * NHEADS * sizeof(float));
    cudaMemsetAsync(attn, 0, (size_t)NN * HC * sizeof(float));
    edge_logits_max<<<EE, 128>>>(q, k, src, dst, ex, m);
    exp_den<<<(EE * NHEADS + 255) / 256, 256>>>(dst, ex, m, den);
    alpha_v_scatter<<<AV_GRID, 256>>>(v, src, dst, ex, den, attn);

    // --- h2 = relu(attn + h @ tskip_W + tskip_b + skip_out)
    gemm_fused<<<grid512, gemm_block>>>(h, ts_W, nullptr, nullptr, ts_b,
                                        attn, skip, h2, NN, 128, 512, 1);

    // --- h3 = relu(h2 @ lin1_W + lin1_b)
    gemm_fused<<<grid128, gemm_block>>>(h2, l1W, nullptr, nullptr, l1b,
                                        nullptr, nullptr, h3, NN, 512, 128, 1);

    // --- gconv l1 with residual
    cudaMemsetAsync(agg, 0, (size_t)NN * HID * sizeof(float));
    scatter_add128<<<SC_GRID, 256>>>(h3, src, dst, agg);
    gemm_fused<<<grid128, gemm_block>>>(agg, g1_Wr, h3, g1_Wroot, g1_br,
                                        h3, nullptr, h4, NN, 128, 128, 1);

    // --- gconv l2 with residual
    cudaMemsetAsync(agg, 0, (size_t)NN * HID * sizeof(float));
    scatter_add128<<<SC_GRID, 256>>>(h4, src, dst, agg);
    gemm_fused<<<grid128, gemm_block>>>(agg, g2_Wr, h4, g2_Wroot, g2_br,
                                        h4, nullptr, h5, NN, 128, 128, 1);

    // --- mean pool + fc
    cudaMemsetAsync(pool, 0, (size_t)GG * HID * sizeof(float));
    cudaMemsetAsync(cnt,  0, (size_t)GG * sizeof(float));
    pool_accum<<<(NN * HID + 255) / 256, 256>>>(h5, batch, pool, cnt);
    pool_fc<<<GG, NCC>>>(pool, cnt, fc_W, fc_b, out);
}

// round 4
// speedup vs baseline: 1.0515x; 1.0515x over previous
#include <cuda_runtime.h>
#include <cuda_bf16.h>
#include <cstdint>

// Problem constants (fixed by the dataset)
#define NN   20000
#define EE   160000
#define HID  128
#define NHEADS 4
#define GG   64
#define NCC  8
#define HC   512

// ---------------------------------------------------------------------------
// Scratch (device globals: allocation-free contract)
// ---------------------------------------------------------------------------
__device__ float g_agg [NN * HID];
__device__ float g_h   [NN * HID];
__device__ float g_h3  [NN * HID];
__device__ float g_h4  [NN * HID];
__device__ float g_h5  [NN * HID];
__device__ float g_skip[NN * HC];
__device__ float g_q   [NN * HC];
__device__ float g_k   [NN * HC];
__device__ float g_v   [NN * HC];
__device__ float g_attn[NN * HC];
__device__ float g_h2  [NN * HC];
__device__ float g_ex  [EE * NHEADS];
__device__ float g_m   [NN * NHEADS];
__device__ float g_den [NN * NHEADS];
__device__ float g_pool[GG * HID];
__device__ float g_cnt [GG];

// ---------------------------------------------------------------------------
// mma.sync bf16 GEMM with 3xBF16 split (hi*hi + hi*lo + lo*hi)
// C[Nrows, Mtot] = op( A@W [+ A2@W2] [+bias] [+add1] [+add2] ), W: [K, Mtot]
// CTA tile 128x128, BK=32. 8 warps (2 m x 4 n), warp tile 64x32.
// mma.m16n8k16: per warp 4 m-tiles x 4 n-tiles, 2 k-steps per chunk.
//
// Smem tiles: bf16 [row][32k], row stride 80 bytes.
//   Fragment quad-load bank index = (20*g + t) mod 32 -> conflict-free.
// ---------------------------------------------------------------------------
#define A_HI 0
#define A_LO 10240
#define B_HI 20480
#define B_LO 30720
#define SSTR 80          // bytes per smem row (32 bf16 + pad)

__device__ __forceinline__ unsigned pack_hi(float x, float y) {
    __nv_bfloat162 p;
    p.x = __float2bfloat16_rn(x);
    p.y = __float2bfloat16_rn(y);
    return *(unsigned*)&p;
}
__device__ __forceinline__ unsigned pack_lo(float x, float y) {
    __nv_bfloat162 p;
    p.x = __float2bfloat16_rn(x - __bfloat162float(__float2bfloat16_rn(x)));
    p.y = __float2bfloat16_rn(y - __bfloat162float(__float2bfloat16_rn(y)));
    return *(unsigned*)&p;
}

__device__ __forceinline__ void mma_bf16(float* c, const unsigned* a, const unsigned* b) {
    asm volatile(
        "mma.sync.aligned.m16n8k16.row.col.f32.bf16.bf16.f32 "
        "{%0,%1,%2,%3}, {%4,%5,%6,%7}, {%8,%9}, {%0,%1,%2,%3};"
        : "+f"(c[0]), "+f"(c[1]), "+f"(c[2]), "+f"(c[3])
        : "r"(a[0]), "r"(a[1]), "r"(a[2]), "r"(a[3]), "r"(b[0]), "r"(b[1]));
}

__global__ void __launch_bounds__(256)
gemm_mma(const float* __restrict__ A,  const float* __restrict__ W,
         const float* __restrict__ A2, const float* __restrict__ W2,
         const float* __restrict__ bias,
         const float* __restrict__ add1, const float* __restrict__ add2,
         float* __restrict__ C, int Nrows, int K, int Mtot, int do_relu)
{
    __shared__ __align__(16) char smem[40960];

    const int tid    = threadIdx.x;
    const int wid    = tid >> 5;
    const int lane   = tid & 31;
    const int warp_m = wid >> 2;          // 0..1
    const int warp_n = wid & 3;           // 0..3
    const int g      = lane >> 2;         // 0..7
    const int t4     = (lane & 3) * 4;    // byte offset of k-pair within row
    const int brow   = blockIdx.x * 128;
    const int bcol   = blockIdx.y * 128;

    float acc[4][4][4];
#pragma unroll
    for (int i = 0; i < 4; i++)
#pragma unroll
        for (int j = 0; j < 4; j++)
#pragma unroll
            for (int r = 0; r < 4; r++) acc[i][j][r] = 0.f;

    for (int pass = 0; pass < 2; ++pass) {
        const float* Ap = pass ? A2 : A;
        const float* Wp = pass ? W2 : W;
        if (!Ap) break;

        for (int k0 = 0; k0 < K; k0 += 32) {
            __syncthreads();   // protect previous chunk's tiles from overwrite

            // ---- A tile: 128 rows x 32 k (fp32 -> bf16 hi/lo)
#pragma unroll
            for (int t = 0; t < 4; ++t) {
                int idx = tid + t * 256;        // 0..1023
                int r   = idx >> 3;             // 0..127
                int kg  = idx & 7;              // 0..7 (float4 within row)
                float4 v = make_float4(0.f, 0.f, 0.f, 0.f);
                if (brow + r < Nrows)
                    v = *(const float4*)(Ap + (size_t)(brow + r) * K + k0 + kg * 4);
                int off = r * SSTR + kg * 8;
                *(uint2*)(smem + A_HI + off) =
                    make_uint2(pack_hi(v.x, v.y), pack_hi(v.z, v.w));
                *(uint2*)(smem + A_LO + off) =
                    make_uint2(pack_lo(v.x, v.y), pack_lo(v.z, v.w));
            }
            // ---- B tile: B[n][k] = W[k0+k][bcol+n], 128 n x 32 k
#pragma unroll
            for (int t = 0; t < 4; ++t) {
                int idx = tid + t * 256;
                int n   = idx & 127;
                int kg  = idx >> 7;             // 0..7
                const float* wp = Wp + (size_t)(k0 + kg * 4) * Mtot + bcol + n;
                float w0 = wp[0];
                float w1 = wp[Mtot];
                float w2 = wp[2 * (size_t)Mtot];
                float w3 = wp[3 * (size_t)Mtot];
                int off = n * SSTR + kg * 8;
                *(uint2*)(smem + B_HI + off) =
                    make_uint2(pack_hi(w0, w1), pack_hi(w2, w3));
                *(uint2*)(smem + B_LO + off) =
                    make_uint2(pack_lo(w0, w1), pack_lo(w2, w3));
            }
            __syncthreads();

            // ---- compute: 2 k-steps of 16
#pragma unroll
            for (int ks = 0; ks < 2; ++ks) {
                const int ko = ks * 32;         // bytes (16 bf16)
                unsigned aH[4][4], aL[4][4], bH[4][2], bL[4][2];
#pragma unroll
                for (int nt = 0; nt < 4; ++nt) {
                    int nb = (warp_n * 32 + nt * 8 + g) * SSTR + t4 + ko;
                    bH[nt][0] = *(const unsigned*)(smem + B_HI + nb);
                    bH[nt][1] = *(const unsigned*)(smem + B_HI + nb + 16);
                    bL[nt][0] = *(const unsigned*)(smem + B_LO + nb);
                    bL[nt][1] = *(const unsigned*)(smem + B_LO + nb + 16);
                }
#pragma unroll
                for (int mt = 0; mt < 4; ++mt) {
                    int mb = (warp_m * 64 + mt * 16 + g) * SSTR + t4 + ko;
                    aH[mt][0] = *(const unsigned*)(smem + A_HI + mb);
                    aH[mt][1] = *(const unsigned*)(smem + A_HI + mb + 8 * SSTR);
                    aH[mt][2] = *(const unsigned*)(smem + A_HI + mb + 16);
                    aH[mt][3] = *(const unsigned*)(smem + A_HI + mb + 8 * SSTR + 16);
                    aL[mt][0] = *(const unsigned*)(smem + A_LO + mb);
                    aL[mt][1] = *(const unsigned*)(smem + A_LO + mb + 8 * SSTR);
                    aL[mt][2] = *(const unsigned*)(smem + A_LO + mb + 16);
                    aL[mt][3] = *(const unsigned*)(smem + A_LO + mb + 8 * SSTR + 16);
                }
#pragma unroll
                for (int mt = 0; mt < 4; ++mt)
#pragma unroll
                    for (int nt = 0; nt < 4; ++nt) {
                        mma_bf16(acc[mt][nt], aH[mt], bH[nt]);
                        mma_bf16(acc[mt][nt], aH[mt], bL[nt]);
                        mma_bf16(acc[mt][nt], aL[mt], bH[nt]);
                    }
            }
        }
    }

    // ---- epilogue: fragments -> global with fused bias/add/add/relu
#pragma unroll
    for (int mt = 0; mt < 4; ++mt) {
#pragma unroll
        for (int nt = 0; nt < 4; ++nt) {
            int col = bcol + warp_n * 32 + nt * 8 + (lane & 3) * 2;
#pragma unroll
            for (int half = 0; half < 2; ++half) {
                int row = brow + warp_m * 64 + mt * 16 + g + half * 8;
                if (row >= Nrows) continue;
                float v0 = acc[mt][nt][half * 2 + 0];
                float v1 = acc[mt][nt][half * 2 + 1];
                if (bias) {
                    float2 b = *(const float2*)(bias + col);
                    v0 += b.x; v1 += b.y;
                }
                size_t o = (size_t)row * Mtot + col;
                if (add1) {
                    float2 a = *(const float2*)(add1 + o);
                    v0 += a.x; v1 += a.y;
                }
                if (add2) {
                    float2 a = *(const float2*)(add2 + o);
                    v0 += a.x; v1 += a.y;
                }
                if (do_relu) { v0 = fmaxf(v0, 0.f); v1 = fmaxf(v1, 0.f); }
                *(float2*)(C + o) = make_float2(v0, v1);
            }
        }
    }
}

// ---------------------------------------------------------------------------
// Edge scatter-add: agg[dst] += in[src] (128 cols)
// ---------------------------------------------------------------------------
__global__ void scatter_add128(const float* __restrict__ in,
                               const int* __restrict__ src,
                               const int* __restrict__ dst,
                               float* __restrict__ agg)
{
    long idx = (long)blockIdx.x * blockDim.x + threadIdx.x;
    if (idx >= (long)EE * 32) return;
    int e = (int)(idx >> 5);
    int c = ((int)idx & 31) * 4;
    int s = src[e], d = dst[e];
    float4 v = *(const float4*)(in + (size_t)s * HID + c);
    float* p = agg + (size_t)d * HID + c;
    atomicAdd(p + 0, v.x);
    atomicAdd(p + 1, v.y);
    atomicAdd(p + 2, v.z);
    atomicAdd(p + 3, v.w);
}

// ---------------------------------------------------------------------------
// Attention
// ---------------------------------------------------------------------------
__device__ __forceinline__ void atomicMaxFloat(float* addr, float val)
{
    int* ia = (int*)addr;
    int old = __float_as_int(*addr);
    while (val > __int_as_float(old)) {
        int assumed = old;
        old = atomicCAS(ia, assumed, __float_as_int(val));
        if (old == assumed) break;
    }
}

__global__ void fill_neg_inf(float* __restrict__ p, int n)
{
    int i = blockIdx.x * blockDim.x + threadIdx.x;
    if (i < n) p[i] = __int_as_float(0xff800000);
}

__global__ void edge_logits_max(const float* __restrict__ q,
                                const float* __restrict__ k,
                                const int* __restrict__ src,
                                const int* __restrict__ dst,
                                float* __restrict__ lg,
                                float* __restrict__ m)
{
    int e    = blockIdx.x;
    int h    = threadIdx.x >> 5;
    int lane = threadIdx.x & 31;
    int d = dst[e], s = src[e];
    float4 qa = *((const float4*)(q + (size_t)d * HC + h * HID) + lane);
    float4 ka = *((const float4*)(k + (size_t)s * HC + h * HID) + lane);
    float sum = qa.x * ka.x + qa.y * ka.y + qa.z * ka.z + qa.w * ka.w;
#pragma unroll
    for (int o = 16; o; o >>= 1) sum += __shfl_xor_sync(0xffffffffu, sum, o);
    if (lane == 0) {
        sum *= 0.08838834764831843f;
        lg[e * NHEADS + h] = sum;
        atomicMaxFloat(&m[d * NHEADS + h], sum);
    }
}

__global__ void exp_den(const int* __restrict__ dst,
                        float* __restrict__ lg,
                        const float* __restrict__ m,
                        float* __restrict__ den)
{
    int i = blockIdx.x * blockDim.x + threadIdx.x;
    if (i >= EE * NHEADS) return;
    int e = i >> 2, h = i & 3;
    int d = dst[e];
    float ex = expf(lg[i] - m[d * NHEADS + h]);
    lg[i] = ex;
    atomicAdd(&den[d * NHEADS + h], ex);
}

__global__ void alpha_v_scatter(const float* __restrict__ v,
                                const int* __restrict__ src,
                                const int* __restrict__ dst,
                                const float* __restrict__ ex,
                                const float* __restrict__ den,
                                float* __restrict__ attn)
{
    long idx = (long)blockIdx.x * blockDim.x + threadIdx.x;
    if (idx >= (long)EE * 128) return;
    int e = (int)(idx >> 7);
    int c = ((int)idx & 127) * 4;
    int h = c >> 7;
    int s = src[e], d = dst[e];
    float alpha = ex[e * NHEADS + h] / (den[d * NHEADS + h] + 1e-16f);
    float4 vv = *(const float4*)(v + (size_t)s * HC + c);
    float* p = attn + (size_t)d * HC + c;
    atomicAdd(p + 0, alpha * vv.x);
    atomicAdd(p + 1, alpha * vv.y);
    atomicAdd(p + 2, alpha * vv.z);
    atomicAdd(p + 3, alpha * vv.w);
}

// ---------------------------------------------------------------------------
// Pooling + final FC
// ---------------------------------------------------------------------------
__global__ void pool_accum(const float* __restrict__ h,
                           const int* __restrict__ batch,
                           float* __restrict__ pool, float* __restrict__ cnt)
{
    int idx = blockIdx.x * blockDim.x + threadIdx.x;
    if (idx >= NN * HID) return;
    int i = idx >> 7, c = idx & 127;
    int b = batch[i];
    atomicAdd(&pool[b * HID + c], h[idx]);
    if (c == 0) atomicAdd(&cnt[b], 1.0f);
}

__global__ void pool_fc(const float* __restrict__ pool,
                        const float* __restrict__ cnt,
                        const float* __restrict__ fcW,
                        const float* __restrict__ fcb,
                        float* __restrict__ out)
{
    int g = blockIdx.x;
    int c = threadIdx.x;
    float inv = 1.f / fmaxf(cnt[g], 1.f);
    float s = 0.f;
    for (int k = 0; k < HID; k++)
        s += pool[g * HID + k] * fcW[k * NCC + c];
    out[g * NCC + c] = s * inv + fcb[c];
}

// ---------------------------------------------------------------------------
// Launch
// ---------------------------------------------------------------------------
extern "C" void kernel_launch(void* const* d_in, const int* in_sizes, int n_in,
                              void* d_out, int out_size)
{
    const float* x        = (const float*)d_in[0];
    const int*   ei       = (const int*)  d_in[1];
    const int*   src      = ei;
    const int*   dst      = ei + EE;
    const int*   batch    = (const int*)  d_in[2];
    const float* c1_Wr    = (const float*)d_in[3];
    const float* c1_br    = (const float*)d_in[4];
    const float* c1_Wroot = (const float*)d_in[5];
    const float* tq_W  = (const float*)d_in[6];  const float* tq_b  = (const float*)d_in[7];
    const float* tk_W  = (const float*)d_in[8];  const float* tk_b  = (const float*)d_in[9];
    const float* tv_W  = (const float*)d_in[10]; const float* tv_b  = (const float*)d_in[11];
    const float* ts_W  = (const float*)d_in[12]; const float* ts_b  = (const float*)d_in[13];
    const float* skip_W = (const float*)d_in[14];
    const float* l1W    = (const float*)d_in[15]; const float* l1b = (const float*)d_in[16];
    const float* g1_Wr = (const float*)d_in[17]; const float* g1_br = (const float*)d_in[18];
    const float* g1_Wroot = (const float*)d_in[19];
    const float* g2_Wr = (const float*)d_in[20]; const float* g2_br = (const float*)d_in[21];
    const float* g2_Wroot = (const float*)d_in[22];
    const float* fc_W = (const float*)d_in[23]; const float* fc_b = (const float*)d_in[24];
    float* out = (float*)d_out;

    float *agg, *h, *h3, *h4, *h5, *skip, *q, *k, *v, *attn, *h2, *ex, *m, *den, *pool, *cnt;
    cudaGetSymbolAddress((void**)&agg,  g_agg);
    cudaGetSymbolAddress((void**)&h,    g_h);
    cudaGetSymbolAddress((void**)&h3,   g_h3);
    cudaGetSymbolAddress((void**)&h4,   g_h4);
    cudaGetSymbolAddress((void**)&h5,   g_h5);
    cudaGetSymbolAddress((void**)&skip, g_skip);
    cudaGetSymbolAddress((void**)&q,    g_q);
    cudaGetSymbolAddress((void**)&k,    g_k);
    cudaGetSymbolAddress((void**)&v,    g_v);
    cudaGetSymbolAddress((void**)&attn, g_attn);
    cudaGetSymbolAddress((void**)&h2,   g_h2);
    cudaGetSymbolAddress((void**)&ex,   g_ex);
    cudaGetSymbolAddress((void**)&m,    g_m);
    cudaGetSymbolAddress((void**)&den,  g_den);
    cudaGetSymbolAddress((void**)&pool, g_pool);
    cudaGetSymbolAddress((void**)&cnt,  g_cnt);

    const dim3 gb(256);
    const dim3 grid128((NN + 127) / 128, 1);   // Mout = 128
    const dim3 grid512((NN + 127) / 128, 4);   // Mout = 512
    const int SC_GRID = (EE * 32 + 255) / 256;
    const int AV_GRID = (EE * 128 + 255) / 256;

    // --- conv1: h = relu( (scatter x) @ Wr + br + x @ Wroot )
    cudaMemsetAsync(agg, 0, (size_t)NN * HID * sizeof(float));
    scatter_add128<<<SC_GRID, 256>>>(x, src, dst, agg);
    gemm_mma<<<grid128, gb>>>(agg, c1_Wr, x, c1_Wroot, c1_br,
                              nullptr, nullptr, h, NN, 128, 128, 1);

    // --- projections off h
    gemm_mma<<<grid512, gb>>>(h, skip_W, nullptr, nullptr, nullptr,
                              nullptr, nullptr, skip, NN, 128, 512, 0);
    gemm_mma<<<grid512, gb>>>(h, tq_W, nullptr, nullptr, tq_b,
                              nullptr, nullptr, q, NN, 128, 512, 0);
    gemm_mma<<<grid512, gb>>>(h, tk_W, nullptr, nullptr, tk_b,
                              nullptr, nullptr, k, NN, 128, 512, 0);
    gemm_mma<<<grid512, gb>>>(h, tv_W, nullptr, nullptr, tv_b,
                              nullptr, nullptr, v, NN, 128, 512, 0);

    // --- edge softmax attention
    fill_neg_inf<<<(NN * NHEADS + 255) / 256, 256>>>(m, NN * NHEADS);
    cudaMemsetAsync(den,  0, (size_t)NN * NHEADS * sizeof(float));
    cudaMemsetAsync(attn, 0, (size_t)NN * HC * sizeof(float));
    edge_logits_max<<<EE, 128>>>(q, k, src, dst, ex, m);
    exp_den<<<(EE * NHEADS + 255) / 256, 256>>>(dst, ex, m, den);
    alpha_v_scatter<<<AV_GRID, 256>>>(v, src, dst, ex, den, attn);

    // --- h2 = relu(attn + h @ tskip_W + tskip_b + skip_out)
    gemm_mma<<<grid512, gb>>>(h, ts_W, nullptr, nullptr, ts_b,
                              attn, skip, h2, NN, 128, 512, 1);

    // --- h3 = relu(h2 @ lin1_W + lin1_b)
    gemm_mma<<<grid128, gb>>>(h2, l1W, nullptr, nullptr, l1b,
                              nullptr, nullptr, h3, NN, 512, 128, 1);

    // --- gconv l1 with residual
    cudaMemsetAsync(agg, 0, (size_t)NN * HID * sizeof(float));
    scatter_add128<<<SC_GRID, 256>>>(h3, src, dst, agg);
    gemm_mma<<<grid128, gb>>>(agg, g1_Wr, h3, g1_Wroot, g1_br,
                              h3, nullptr, h4, NN, 128, 128, 1);

    // --- gconv l2 with residual
    cudaMemsetAsync(agg, 0, (size_t)NN * HID * sizeof(float));
    scatter_add128<<<SC_GRID, 256>>>(h4, src, dst, agg);
    gemm_mma<<<grid128, gb>>>(agg, g2_Wr, h4, g2_Wroot, g2_br,
                              h4, nullptr, h5, NN, 128, 128, 1);

    // --- mean pool + fc
    cudaMemsetAsync(pool, 0, (size_t)GG * HID * sizeof(float));
    cudaMemsetAsync(cnt,  0, (size_t)GG * sizeof(float));
    pool_accum<<<(NN * HID + 255) / 256, 256>>>(h5, batch, pool, cnt);
    pool_fc<<<GG, NCC>>>(pool, cnt, fc_W, fc_b, out);
}

// round 5
// speedup vs baseline: 1.8134x; 1.7245x over previous
#include <cuda_runtime.h>
#include <cuda_bf16.h>
#include <cstdint>
#include <math_constants.h>

// Problem constants (fixed by the dataset)
#define NN   20000
#define EE   160000
#define HID  128
#define NHEADS 4
#define GG   64
#define NCC  8
#define HC   512

// ---------------------------------------------------------------------------
// Scratch (device globals: allocation-free contract)
// ---------------------------------------------------------------------------
__device__ float g_agg [NN * HID];
__device__ float g_h   [NN * HID];
__device__ float g_h3  [NN * HID];
__device__ float g_h4  [NN * HID];
__device__ float g_h5  [NN * HID];
__device__ float g_skip[NN * HC];
__device__ float g_q   [NN * HC];
__device__ float g_k   [NN * HC];
__device__ float g_v   [NN * HC];
__device__ float g_attn[NN * HC];
__device__ float g_h2  [NN * HC];
__device__ float g_pool[GG * HID];
__device__ float g_cnt [GG];
// CSR (by dst)
__device__ int   g_deg [NN];
__device__ int   g_cur [NN];
__device__ int   g_off [NN + 1];
__device__ int   g_eid [EE];

// ---------------------------------------------------------------------------
// mma.sync bf16 GEMM with 3xBF16 split (hi*hi + hi*lo + lo*hi)
// C[Nrows, Mtot] = op( A@W [+ A2@W2] [+bias] [+add1] [+add2] ), W: [K, Mtot]
// CTA tile 128x64, BK=32. 8 warps (2 m x 4 n), warp tile 64x16.
// 2 CTAs/SM (launch_bounds) so one CTA's loads overlap the other's MMAs.
// Smem rows stride 80B -> quad-load bank = (20g + t) mod 32, conflict-free.
// ---------------------------------------------------------------------------
#define A_HI 0
#define A_LO 10240
#define B_HI 20480
#define B_LO 25600
#define SSTR 80

__device__ __forceinline__ unsigned pack_hi(float x, float y) {
    __nv_bfloat162 p;
    p.x = __float2bfloat16_rn(x);
    p.y = __float2bfloat16_rn(y);
    return *(unsigned*)&p;
}
__device__ __forceinline__ unsigned pack_lo(float x, float y) {
    __nv_bfloat162 p;
    p.x = __float2bfloat16_rn(x - __bfloat162float(__float2bfloat16_rn(x)));
    p.y = __float2bfloat16_rn(y - __bfloat162float(__float2bfloat16_rn(y)));
    return *(unsigned*)&p;
}

__device__ __forceinline__ void mma_bf16(float* c, const unsigned* a, const unsigned* b) {
    asm volatile(
        "mma.sync.aligned.m16n8k16.row.col.f32.bf16.bf16.f32 "
        "{%0,%1,%2,%3}, {%4,%5,%6,%7}, {%8,%9}, {%0,%1,%2,%3};"
        : "+f"(c[0]), "+f"(c[1]), "+f"(c[2]), "+f"(c[3])
        : "r"(a[0]), "r"(a[1]), "r"(a[2]), "r"(a[3]), "r"(b[0]), "r"(b[1]));
}

__global__ void __launch_bounds__(256, 2)
gemm_mma(const float* __restrict__ A,  const float* __restrict__ W,
         const float* __restrict__ A2, const float* __restrict__ W2,
         const float* __restrict__ bias,
         const float* __restrict__ add1, const float* __restrict__ add2,
         float* __restrict__ C, int Nrows, int K, int Mtot, int do_relu)
{
    __shared__ __align__(16) char smem[30720];

    const int tid    = threadIdx.x;
    const int wid    = tid >> 5;
    const int lane   = tid & 31;
    const int warp_m = wid >> 2;          // 0..1 (64 rows each)
    const int warp_n = wid & 3;           // 0..3 (16 cols each)
    const int g      = lane >> 2;         // 0..7
    const int t4     = (lane & 3) * 4;    // byte offset of k-pair within row
    const int brow   = blockIdx.x * 128;
    const int bcol   = blockIdx.y * 64;

    float acc[4][2][4];
#pragma unroll
    for (int i = 0; i < 4; i++)
#pragma unroll
        for (int j = 0; j < 2; j++)
#pragma unroll
            for (int r = 0; r < 4; r++) acc[i][j][r] = 0.f;

    for (int pass = 0; pass < 2; ++pass) {
        const float* Ap = pass ? A2 : A;
        const float* Wp = pass ? W2 : W;
        if (!Ap) break;

        for (int k0 = 0; k0 < K; k0 += 32) {
            __syncthreads();   // protect previous chunk's tiles

            // ---- A tile: 128 rows x 32 k (fp32 -> bf16 hi/lo)
#pragma unroll
            for (int t = 0; t < 4; ++t) {
                int idx = tid + t * 256;        // 0..1023
                int r   = idx >> 3;             // 0..127
                int kg  = idx & 7;              // 0..7
                float4 v = make_float4(0.f, 0.f, 0.f, 0.f);
                if (brow + r < Nrows)
                    v = *(const float4*)(Ap + (size_t)(brow + r) * K + k0 + kg * 4);
                int off = r * SSTR + kg * 8;
                *(uint2*)(smem + A_HI + off) =
                    make_uint2(pack_hi(v.x, v.y), pack_hi(v.z, v.w));
                *(uint2*)(smem + A_LO + off) =
                    make_uint2(pack_lo(v.x, v.y), pack_lo(v.z, v.w));
            }
            // ---- B tile: B[n][k] = W[k0+k][bcol+n], 64 n x 32 k
#pragma unroll
            for (int t = 0; t < 2; ++t) {
                int idx = tid + t * 256;        // 0..511
                int n   = idx & 63;
                int kg  = idx >> 6;             // 0..7
                const float* wp = Wp + (size_t)(k0 + kg * 4) * Mtot + bcol + n;
                float w0 = wp[0];
                float w1 = wp[Mtot];
                float w2 = wp[2 * (size_t)Mtot];
                float w3 = wp[3 * (size_t)Mtot];
                int off = n * SSTR + kg * 8;
                *(uint2*)(smem + B_HI + off) =
                    make_uint2(pack_hi(w0, w1), pack_hi(w2, w3));
                *(uint2*)(smem + B_LO + off) =
                    make_uint2(pack_lo(w0, w1), pack_lo(w2, w3));
            }
            __syncthreads();

            // ---- compute: 2 k-steps of 16
#pragma unroll
            for (int ks = 0; ks < 2; ++ks) {
                const int ko = ks * 32;         // bytes (16 bf16)
                unsigned aH[4][4], aL[4][4], bH[2][2], bL[2][2];
#pragma unroll
                for (int nt = 0; nt < 2; ++nt) {
                    int nb = (warp_n * 16 + nt * 8 + g) * SSTR + t4 + ko;
                    bH[nt][0] = *(const unsigned*)(smem + B_HI + nb);
                    bH[nt][1] = *(const unsigned*)(smem + B_HI + nb + 16);
                    bL[nt][0] = *(const unsigned*)(smem + B_LO + nb);
                    bL[nt][1] = *(const unsigned*)(smem + B_LO + nb + 16);
                }
#pragma unroll
                for (int mt = 0; mt < 4; ++mt) {
                    int mb = (warp_m * 64 + mt * 16 + g) * SSTR + t4 + ko;
                    aH[mt][0] = *(const unsigned*)(smem + A_HI + mb);
                    aH[mt][1] = *(const unsigned*)(smem + A_HI + mb + 8 * SSTR);
                    aH[mt][2] = *(const unsigned*)(smem + A_HI + mb + 16);
                    aH[mt][3] = *(const unsigned*)(smem + A_HI + mb + 8 * SSTR + 16);
                    aL[mt][0] = *(const unsigned*)(smem + A_LO + mb);
                    aL[mt][1] = *(const unsigned*)(smem + A_LO + mb + 8 * SSTR);
                    aL[mt][2] = *(const unsigned*)(smem + A_LO + mb + 16);
                    aL[mt][3] = *(const unsigned*)(smem + A_LO + mb + 8 * SSTR + 16);
                }
#pragma unroll
                for (int mt = 0; mt < 4; ++mt)
#pragma unroll
                    for (int nt = 0; nt < 2; ++nt) {
                        mma_bf16(acc[mt][nt], aH[mt], bH[nt]);
                        mma_bf16(acc[mt][nt], aH[mt], bL[nt]);
                        mma_bf16(acc[mt][nt], aL[mt], bH[nt]);
                    }
            }
        }
    }

    // ---- epilogue: fragments -> global with fused bias/add/add/relu
#pragma unroll
    for (int mt = 0; mt < 4; ++mt) {
#pragma unroll
        for (int nt = 0; nt < 2; ++nt) {
            int col = bcol + warp_n * 16 + nt * 8 + (lane & 3) * 2;
#pragma unroll
            for (int half = 0; half < 2; ++half) {
                int row = brow + warp_m * 64 + mt * 16 + g + half * 8;
                if (row >= Nrows) continue;
                float v0 = acc[mt][nt][half * 2 + 0];
                float v1 = acc[mt][nt][half * 2 + 1];
                if (bias) {
                    float2 b = *(const float2*)(bias + col);
                    v0 += b.x; v1 += b.y;
                }
                size_t o = (size_t)row * Mtot + col;
                if (add1) {
                    float2 a = *(const float2*)(add1 + o);
                    v0 += a.x; v1 += a.y;
                }
                if (add2) {
                    float2 a = *(const float2*)(add2 + o);
                    v0 += a.x; v1 += a.y;
                }
                if (do_relu) { v0 = fmaxf(v0, 0.f); v1 = fmaxf(v1, 0.f); }
                *(float2*)(C + o) = make_float2(v0, v1);
            }
        }
    }
}

// ---------------------------------------------------------------------------
// CSR build (by dst)
// ---------------------------------------------------------------------------
__global__ void deg_count(const int* __restrict__ dst, int* __restrict__ deg)
{
    int e = blockIdx.x * blockDim.x + threadIdx.x;
    if (e < EE) atomicAdd(&deg[dst[e]], 1);
}

// single block, 1024 threads: exclusive scan of deg -> off (and cur copy)
__global__ void scan_offsets(const int* __restrict__ deg,
                             int* __restrict__ off, int* __restrict__ cur)
{
    __shared__ int part[1024];
    const int t  = threadIdx.x;
    const int CH = (NN + 1023) / 1024;   // 20
    int base = t * CH;
    int s = 0;
    for (int i = 0; i < CH; i++) {
        int idx = base + i;
        if (idx < NN) s += deg[idx];
    }
    part[t] = s;
    __syncthreads();
    for (int o = 1; o < 1024; o <<= 1) {
        int v = (t >= o) ? part[t - o] : 0;
        __syncthreads();
        part[t] += v;
        __syncthreads();
    }
    int excl = (t == 0) ? 0 : part[t - 1];
    for (int i = 0; i < CH; i++) {
        int idx = base + i;
        if (idx < NN) {
            off[idx] = excl;
            cur[idx] = excl;
            excl += deg[idx];
        }
    }
    if (t == 1023) off[NN] = part[1023];
}

__global__ void build_eidx(const int* __restrict__ dst,
                           int* __restrict__ cur, int* __restrict__ eid)
{
    int e = blockIdx.x * blockDim.x + threadIdx.x;
    if (e >= EE) return;
    int pos = atomicAdd(&cur[dst[e]], 1);
    eid[pos] = e;
}

// ---------------------------------------------------------------------------
// GraphConv aggregation via CSR: agg[d] = sum_{e: dst=d} in[src[e]]
// One block (128 threads) per node; no atomics, no memset.
// ---------------------------------------------------------------------------
__global__ void gconv_agg(const float* __restrict__ in,
                          const int* __restrict__ src,
                          const int* __restrict__ off,
                          const int* __restrict__ eid,
                          float* __restrict__ agg)
{
    int d = blockIdx.x;
    int c = threadIdx.x;      // 0..127
    int e0 = off[d], e1 = off[d + 1];
    float s = 0.f;
    for (int i = e0; i < e1; ++i)
        s += in[(size_t)src[eid[i]] * HID + c];
    agg[(size_t)d * HID + c] = s;
}

// ---------------------------------------------------------------------------
// TransformerConv attention via CSR: single-pass online softmax per node.
// Block = node, warp = head. q loaded once; k,v gathered once per edge.
// ---------------------------------------------------------------------------
__global__ void attn_node(const float* __restrict__ q,
                          const float* __restrict__ k,
                          const float* __restrict__ v,
                          const int* __restrict__ src,
                          const int* __restrict__ off,
                          const int* __restrict__ eid,
                          float* __restrict__ attn)
{
    int d    = blockIdx.x;
    int h    = threadIdx.x >> 5;
    int lane = threadIdx.x & 31;
    int e0 = off[d], e1 = off[d + 1];

    float4 qv = *((const float4*)(q + (size_t)d * HC + h * HID) + lane);
    float4 acc = make_float4(0.f, 0.f, 0.f, 0.f);
    float mrun = -CUDART_INF_F, den = 0.f;

    for (int i = e0; i < e1; ++i) {
        int s = src[eid[i]];
        float4 kv = *((const float4*)(k + (size_t)s * HC + h * HID) + lane);
        float dot = qv.x * kv.x + qv.y * kv.y + qv.z * kv.z + qv.w * kv.w;
#pragma unroll
        for (int o = 16; o; o >>= 1) dot += __shfl_xor_sync(0xffffffffu, dot, o);
        dot *= 0.08838834764831843f;     // 1/sqrt(128)
        float mnew = fmaxf(mrun, dot);
        float corr = expf(mrun - mnew);  // first edge: exp(-inf) = 0
        float w    = expf(dot - mnew);
        den = den * corr + w;
        float4 vv = *((const float4*)(v + (size_t)s * HC + h * HID) + lane);
        acc.x = acc.x * corr + w * vv.x;
        acc.y = acc.y * corr + w * vv.y;
        acc.z = acc.z * corr + w * vv.z;
        acc.w = acc.w * corr + w * vv.w;
        mrun = mnew;
    }
    float inv = 1.f / (den + 1e-16f);
    *((float4*)(attn + (size_t)d * HC + h * HID) + lane) =
        make_float4(acc.x * inv, acc.y * inv, acc.z * inv, acc.w * inv);
}

// ---------------------------------------------------------------------------
// Pooling + final FC
// ---------------------------------------------------------------------------
__global__ void pool_accum(const float* __restrict__ h,
                           const int* __restrict__ batch,
                           float* __restrict__ pool, float* __restrict__ cnt)
{
    int idx = blockIdx.x * blockDim.x + threadIdx.x;
    if (idx >= NN * HID) return;
    int i = idx >> 7, c = idx & 127;
    int b = batch[i];
    atomicAdd(&pool[b * HID + c], h[idx]);
    if (c == 0) atomicAdd(&cnt[b], 1.0f);
}

__global__ void pool_fc(const float* __restrict__ pool,
                        const float* __restrict__ cnt,
                        const float* __restrict__ fcW,
                        const float* __restrict__ fcb,
                        float* __restrict__ out)
{
    int g = blockIdx.x;
    int c = threadIdx.x;
    float inv = 1.f / fmaxf(cnt[g], 1.f);
    float s = 0.f;
    for (int k = 0; k < HID; k++)
        s += pool[g * HID + k] * fcW[k * NCC + c];
    out[g * NCC + c] = s * inv + fcb[c];
}

// ---------------------------------------------------------------------------
// Launch
// ---------------------------------------------------------------------------
extern "C" void kernel_launch(void* const* d_in, const int* in_sizes, int n_in,
                              void* d_out, int out_size)
{
    const float* x        = (const float*)d_in[0];
    const int*   ei       = (const int*)  d_in[1];
    const int*   src      = ei;
    const int*   dst      = ei + EE;
    const int*   batch    = (const int*)  d_in[2];
    const float* c1_Wr    = (const float*)d_in[3];
    const float* c1_br    = (const float*)d_in[4];
    const float* c1_Wroot = (const float*)d_in[5];
    const float* tq_W  = (const float*)d_in[6];  const float* tq_b  = (const float*)d_in[7];
    const float* tk_W  = (const float*)d_in[8];  const float* tk_b  = (const float*)d_in[9];
    const float* tv_W  = (const float*)d_in[10]; const float* tv_b  = (const float*)d_in[11];
    const float* ts_W  = (const float*)d_in[12]; const float* ts_b  = (const float*)d_in[13];
    const float* skip_W = (const float*)d_in[14];
    const float* l1W    = (const float*)d_in[15]; const float* l1b = (const float*)d_in[16];
    const float* g1_Wr = (const float*)d_in[17]; const float* g1_br = (const float*)d_in[18];
    const float* g1_Wroot = (const float*)d_in[19];
    const float* g2_Wr = (const float*)d_in[20]; const float* g2_br = (const float*)d_in[21];
    const float* g2_Wroot = (const float*)d_in[22];
    const float* fc_W = (const float*)d_in[23]; const float* fc_b = (const float*)d_in[24];
    float* out = (float*)d_out;

    float *agg, *h, *h3, *h4, *h5, *skip, *q, *k, *v, *attn, *h2, *pool, *cnt;
    int *deg, *cur, *off, *eid;
    cudaGetSymbolAddress((void**)&agg,  g_agg);
    cudaGetSymbolAddress((void**)&h,    g_h);
    cudaGetSymbolAddress((void**)&h3,   g_h3);
    cudaGetSymbolAddress((void**)&h4,   g_h4);
    cudaGetSymbolAddress((void**)&h5,   g_h5);
    cudaGetSymbolAddress((void**)&skip, g_skip);
    cudaGetSymbolAddress((void**)&q,    g_q);
    cudaGetSymbolAddress((void**)&k,    g_k);
    cudaGetSymbolAddress((void**)&v,    g_v);
    cudaGetSymbolAddress((void**)&attn, g_attn);
    cudaGetSymbolAddress((void**)&h2,   g_h2);
    cudaGetSymbolAddress((void**)&pool, g_pool);
    cudaGetSymbolAddress((void**)&cnt,  g_cnt);
    cudaGetSymbolAddress((void**)&deg,  g_deg);
    cudaGetSymbolAddress((void**)&cur,  g_cur);
    cudaGetSymbolAddress((void**)&off,  g_off);
    cudaGetSymbolAddress((void**)&eid,  g_eid);

    const dim3 gb(256);
    const dim3 grid128((NN + 127) / 128, 2);   // Mout = 128
    const dim3 grid512((NN + 127) / 128, 8);   // Mout = 512

    // --- CSR build (by dst)
    cudaMemsetAsync(deg, 0, NN * sizeof(int));
    deg_count<<<(EE + 255) / 256, 256>>>(dst, deg);
    scan_offsets<<<1, 1024>>>(deg, off, cur);
    build_eidx<<<(EE + 255) / 256, 256>>>(dst, cur, eid);

    // --- conv1: h = relu( (agg x) @ Wr + br + x @ Wroot )
    gconv_agg<<<NN, 128>>>(x, src, off, eid, agg);
    gemm_mma<<<grid128, gb>>>(agg, c1_Wr, x, c1_Wroot, c1_br,
                              nullptr, nullptr, h, NN, 128, 128, 1);

    // --- projections off h
    gemm_mma<<<grid512, gb>>>(h, skip_W, nullptr, nullptr, nullptr,
                              nullptr, nullptr, skip, NN, 128, 512, 0);
    gemm_mma<<<grid512, gb>>>(h, tq_W, nullptr, nullptr, tq_b,
                              nullptr, nullptr, q, NN, 128, 512, 0);
    gemm_mma<<<grid512, gb>>>(h, tk_W, nullptr, nullptr, tk_b,
                              nullptr, nullptr, k, NN, 128, 512, 0);
    gemm_mma<<<grid512, gb>>>(h, tv_W, nullptr, nullptr, tv_b,
                              nullptr, nullptr, v, NN, 128, 512, 0);

    // --- attention (single pass, no atomics)
    attn_node<<<NN, 128>>>(q, k, v, src, off, eid, attn);

    // --- h2 = relu(attn + h @ tskip_W + tskip_b + skip_out)
    gemm_mma<<<grid512, gb>>>(h, ts_W, nullptr, nullptr, ts_b,
                              attn, skip, h2, NN, 128, 512, 1);

    // --- h3 = relu(h2 @ lin1_W + lin1_b)
    gemm_mma<<<grid128, gb>>>(h2, l1W, nullptr, nullptr, l1b,
                              nullptr, nullptr, h3, NN, 512, 128, 1);

    // --- gconv l1 with residual
    gconv_agg<<<NN, 128>>>(h3, src, off, eid, agg);
    gemm_mma<<<grid128, gb>>>(agg, g1_Wr, h3, g1_Wroot, g1_br,
                              h3, nullptr, h4, NN, 128, 128, 1);

    // --- gconv l2 with residual
    gconv_agg<<<NN, 128>>>(h4, src, off, eid, agg);
    gemm_mma<<<grid128, gb>>>(agg, g2_Wr, h4, g2_Wroot, g2_br,
                              h4, nullptr, h5, NN, 128, 128, 1);

    // --- mean pool + fc
    cudaMemsetAsync(pool, 0, (size_t)GG * HID * sizeof(float));
    cudaMemsetAsync(cnt,  0, (size_t)GG * sizeof(float));
    pool_accum<<<(NN * HID + 255) / 256, 256>>>(h5, batch, pool, cnt);
    pool_fc<<<GG, NCC>>>(pool, cnt, fc_W, fc_b, out);
}

// round 6
// speedup vs baseline: 1.9796x; 1.0916x over previous
#include <cuda_runtime.h>
#include <cuda_bf16.h>
#include <cstdint>
#include <math_constants.h>

// Problem constants (fixed by the dataset)
#define NN   20000
#define EE   160000
#define HID  128
#define NHEADS 4
#define GG   64
#define NCC  8
#define HC   512
#define MPK  2560      // packed projection width: [skip | q | k | v | ts]

// ---------------------------------------------------------------------------
// Scratch (device globals: allocation-free contract)
// ---------------------------------------------------------------------------
__device__ float g_agg [NN * HID];
__device__ float g_h   [NN * HID];
__device__ float g_h3  [NN * HID];
__device__ float g_h4  [NN * HID];
__device__ float g_h5  [NN * HID];
__device__ float g_pack[(size_t)NN * MPK];   // packed projection outputs
__device__ float g_h2  [NN * HC];
__device__ float g_Wpk [HID * MPK];
__device__ float g_bpk [MPK];
__device__ float g_pool[GG * HID];
__device__ float g_cnt [GG];
// CSR (by dst)
__device__ int   g_deg [NN];
__device__ int   g_cur [NN];
__device__ int   g_off [NN + 1];
__device__ int   g_srcs[EE];    // src node ids in dst-CSR order

// ---------------------------------------------------------------------------
// mma.sync bf16 GEMM with 3xBF16 split (hi*hi + hi*lo + lo*hi)
// C[Nrows, Mtot] = op( A@W [+ A2@W2] [+bias] [+add1] ), W: [K, Mtot]
// CTA tile 128x64, BK=32. 8 warps (2 m x 4 n), warp tile 64x16. 2 CTAs/SM.
// ---------------------------------------------------------------------------
#define A_HI 0
#define A_LO 10240
#define B_HI 20480
#define B_LO 25600
#define SSTR 80

__device__ __forceinline__ unsigned pack_hi(float x, float y) {
    __nv_bfloat162 p;
    p.x = __float2bfloat16_rn(x);
    p.y = __float2bfloat16_rn(y);
    return *(unsigned*)&p;
}
__device__ __forceinline__ unsigned pack_lo(float x, float y) {
    __nv_bfloat162 p;
    p.x = __float2bfloat16_rn(x - __bfloat162float(__float2bfloat16_rn(x)));
    p.y = __float2bfloat16_rn(y - __bfloat162float(__float2bfloat16_rn(y)));
    return *(unsigned*)&p;
}

__device__ __forceinline__ void mma_bf16(float* c, const unsigned* a, const unsigned* b) {
    asm volatile(
        "mma.sync.aligned.m16n8k16.row.col.f32.bf16.bf16.f32 "
        "{%0,%1,%2,%3}, {%4,%5,%6,%7}, {%8,%9}, {%0,%1,%2,%3};"
        : "+f"(c[0]), "+f"(c[1]), "+f"(c[2]), "+f"(c[3])
        : "r"(a[0]), "r"(a[1]), "r"(a[2]), "r"(a[3]), "r"(b[0]), "r"(b[1]));
}

__global__ void __launch_bounds__(256, 2)
gemm_mma(const float* __restrict__ A,  const float* __restrict__ W,
         const float* __restrict__ A2, const float* __restrict__ W2,
         const float* __restrict__ bias,
         const float* __restrict__ add1,
         float* __restrict__ C, int Nrows, int K, int Mtot, int do_relu)
{
    __shared__ __align__(16) char smem[30720];

    const int tid    = threadIdx.x;
    const int wid    = tid >> 5;
    const int lane   = tid & 31;
    const int warp_m = wid >> 2;
    const int warp_n = wid & 3;
    const int g      = lane >> 2;
    const int t4     = (lane & 3) * 4;
    const int brow   = blockIdx.x * 128;
    const int bcol   = blockIdx.y * 64;

    float acc[4][2][4];
#pragma unroll
    for (int i = 0; i < 4; i++)
#pragma unroll
        for (int j = 0; j < 2; j++)
#pragma unroll
            for (int r = 0; r < 4; r++) acc[i][j][r] = 0.f;

    for (int pass = 0; pass < 2; ++pass) {
        const float* Ap = pass ? A2 : A;
        const float* Wp = pass ? W2 : W;
        if (!Ap) break;

        for (int k0 = 0; k0 < K; k0 += 32) {
            __syncthreads();

            // ---- A tile: 128 rows x 32 k (fp32 -> bf16 hi/lo)
#pragma unroll
            for (int t = 0; t < 4; ++t) {
                int idx = tid + t * 256;
                int r   = idx >> 3;
                int kg  = idx & 7;
                float4 v = make_float4(0.f, 0.f, 0.f, 0.f);
                if (brow + r < Nrows)
                    v = *(const float4*)(Ap + (size_t)(brow + r) * K + k0 + kg * 4);
                int off = r * SSTR + kg * 8;
                *(uint2*)(smem + A_HI + off) =
                    make_uint2(pack_hi(v.x, v.y), pack_hi(v.z, v.w));
                *(uint2*)(smem + A_LO + off) =
                    make_uint2(pack_lo(v.x, v.y), pack_lo(v.z, v.w));
            }
            // ---- B tile: 64 n x 32 k
#pragma unroll
            for (int t = 0; t < 2; ++t) {
                int idx = tid + t * 256;
                int n   = idx & 63;
                int kg  = idx >> 6;
                const float* wp = Wp + (size_t)(k0 + kg * 4) * Mtot + bcol + n;
                float w0 = wp[0];
                float w1 = wp[Mtot];
                float w2 = wp[2 * (size_t)Mtot];
                float w3 = wp[3 * (size_t)Mtot];
                int off = n * SSTR + kg * 8;
                *(uint2*)(smem + B_HI + off) =
                    make_uint2(pack_hi(w0, w1), pack_hi(w2, w3));
                *(uint2*)(smem + B_LO + off) =
                    make_uint2(pack_lo(w0, w1), pack_lo(w2, w3));
            }
            __syncthreads();

#pragma unroll
            for (int ks = 0; ks < 2; ++ks) {
                const int ko = ks * 32;
                unsigned aH[4][4], aL[4][4], bH[2][2], bL[2][2];
#pragma unroll
                for (int nt = 0; nt < 2; ++nt) {
                    int nb = (warp_n * 16 + nt * 8 + g) * SSTR + t4 + ko;
                    bH[nt][0] = *(const unsigned*)(smem + B_HI + nb);
                    bH[nt][1] = *(const unsigned*)(smem + B_HI + nb + 16);
                    bL[nt][0] = *(const unsigned*)(smem + B_LO + nb);
                    bL[nt][1] = *(const unsigned*)(smem + B_LO + nb + 16);
                }
#pragma unroll
                for (int mt = 0; mt < 4; ++mt) {
                    int mb = (warp_m * 64 + mt * 16 + g) * SSTR + t4 + ko;
                    aH[mt][0] = *(const unsigned*)(smem + A_HI + mb);
                    aH[mt][1] = *(const unsigned*)(smem + A_HI + mb + 8 * SSTR);
                    aH[mt][2] = *(const unsigned*)(smem + A_HI + mb + 16);
                    aH[mt][3] = *(const unsigned*)(smem + A_HI + mb + 8 * SSTR + 16);
                    aL[mt][0] = *(const unsigned*)(smem + A_LO + mb);
                    aL[mt][1] = *(const unsigned*)(smem + A_LO + mb + 8 * SSTR);
                    aL[mt][2] = *(const unsigned*)(smem + A_LO + mb + 16);
                    aL[mt][3] = *(const unsigned*)(smem + A_LO + mb + 8 * SSTR + 16);
                }
#pragma unroll
                for (int mt = 0; mt < 4; ++mt)
#pragma unroll
                    for (int nt = 0; nt < 2; ++nt) {
                        mma_bf16(acc[mt][nt], aH[mt], bH[nt]);
                        mma_bf16(acc[mt][nt], aH[mt], bL[nt]);
                        mma_bf16(acc[mt][nt], aL[mt], bH[nt]);
                    }
            }
        }
    }

    // ---- epilogue
#pragma unroll
    for (int mt = 0; mt < 4; ++mt) {
#pragma unroll
        for (int nt = 0; nt < 2; ++nt) {
            int col = bcol + warp_n * 16 + nt * 8 + (lane & 3) * 2;
#pragma unroll
            for (int half = 0; half < 2; ++half) {
                int row = brow + warp_m * 64 + mt * 16 + g + half * 8;
                if (row >= Nrows) continue;
                float v0 = acc[mt][nt][half * 2 + 0];
                float v1 = acc[mt][nt][half * 2 + 1];
                if (bias) {
                    float2 b = *(const float2*)(bias + col);
                    v0 += b.x; v1 += b.y;
                }
                size_t o = (size_t)row * Mtot + col;
                if (add1) {
                    float2 a = *(const float2*)(add1 + o);
                    v0 += a.x; v1 += a.y;
                }
                if (do_relu) { v0 = fmaxf(v0, 0.f); v1 = fmaxf(v1, 0.f); }
                *(float2*)(C + o) = make_float2(v0, v1);
            }
        }
    }
}

// ---------------------------------------------------------------------------
// Weight/bias packing for the 5-way projection GEMM
// ---------------------------------------------------------------------------
__global__ void pack_weights(const float* __restrict__ w0,  // skip (no bias)
                             const float* __restrict__ w1,  // q
                             const float* __restrict__ w2,  // k
                             const float* __restrict__ w3,  // v
                             const float* __restrict__ w4,  // ts
                             float* __restrict__ Wp)
{
    int idx = blockIdx.x * blockDim.x + threadIdx.x;   // float4 over 128*2560
    if (idx >= HID * MPK / 4) return;
    int row = idx / (MPK / 4);
    int c4  = idx % (MPK / 4);
    int col = c4 * 4;
    int b   = col >> 9;              // 0..4
    int c   = col & 511;
    const float* srcs[5] = {w0, w1, w2, w3, w4};
    *(float4*)(Wp + (size_t)row * MPK + col) =
        *(const float4*)(srcs[b] + (size_t)row * HC + c);
}

__global__ void pack_bias(const float* __restrict__ b1, const float* __restrict__ b2,
                          const float* __restrict__ b3, const float* __restrict__ b4,
                          float* __restrict__ bp)
{
    int col = blockIdx.x * blockDim.x + threadIdx.x;
    if (col >= MPK) return;
    int b = col >> 9, c = col & 511;
    float v = 0.f;
    if (b == 1) v = b1[c];
    else if (b == 2) v = b2[c];
    else if (b == 3) v = b3[c];
    else if (b == 4) v = b4[c];
    bp[col] = v;
}

// ---------------------------------------------------------------------------
// CSR build (by dst), storing src ids directly in CSR order
// ---------------------------------------------------------------------------
__global__ void deg_count(const int* __restrict__ dst, int* __restrict__ deg)
{
    int e = blockIdx.x * blockDim.x + threadIdx.x;
    if (e < EE) atomicAdd(&deg[dst[e]], 1);
}

__global__ void scan_offsets(const int* __restrict__ deg,
                             int* __restrict__ off, int* __restrict__ cur)
{
    __shared__ int part[1024];
    const int t  = threadIdx.x;
    const int CH = (NN + 1023) / 1024;
    int base = t * CH;
    int s = 0;
    for (int i = 0; i < CH; i++) {
        int idx = base + i;
        if (idx < NN) s += deg[idx];
    }
    part[t] = s;
    __syncthreads();
    for (int o = 1; o < 1024; o <<= 1) {
        int v = (t >= o) ? part[t - o] : 0;
        __syncthreads();
        part[t] += v;
        __syncthreads();
    }
    int excl = (t == 0) ? 0 : part[t - 1];
    for (int i = 0; i < CH; i++) {
        int idx = base + i;
        if (idx < NN) {
            off[idx] = excl;
            cur[idx] = excl;
            excl += deg[idx];
        }
    }
    if (t == 1023) off[NN] = part[1023];
}

__global__ void build_srcs(const int* __restrict__ src, const int* __restrict__ dst,
                           int* __restrict__ cur, int* __restrict__ srcs)
{
    int e = blockIdx.x * blockDim.x + threadIdx.x;
    if (e >= EE) return;
    int pos = atomicAdd(&cur[dst[e]], 1);
    srcs[pos] = src[e];
}

// ---------------------------------------------------------------------------
// GraphConv aggregation via CSR (unroll x4 for MLP)
// ---------------------------------------------------------------------------
__global__ void gconv_agg(const float* __restrict__ in,
                          const int* __restrict__ off,
                          const int* __restrict__ srcs,
                          float* __restrict__ agg)
{
    int d = blockIdx.x;
    int c = threadIdx.x;
    int e0 = off[d], e1 = off[d + 1];
    float s = 0.f;
    int i = e0;
    for (; i + 3 < e1; i += 4) {
        int s0 = srcs[i], s1 = srcs[i + 1], s2 = srcs[i + 2], s3 = srcs[i + 3];
        s += in[(size_t)s0 * HID + c] + in[(size_t)s1 * HID + c]
           + in[(size_t)s2 * HID + c] + in[(size_t)s3 * HID + c];
    }
    for (; i < e1; ++i)
        s += in[(size_t)srcs[i] * HID + c];
    agg[(size_t)d * HID + c] = s;
}

// ---------------------------------------------------------------------------
// Attention + transformer epilogue fused:
//   h2[d] = relu( softmax-attn(d) + ts[d] + skip[d] )
// q,k,v,skip,ts are column slices of the packed projection (row stride MPK).
// Block = node, warp = head. Online softmax, edge loop unrolled x2.
// ---------------------------------------------------------------------------
__global__ void attn_fused(const float* __restrict__ pack,
                           const int* __restrict__ off,
                           const int* __restrict__ srcs,
                           float* __restrict__ h2)
{
    int d    = blockIdx.x;
    int h    = threadIdx.x >> 5;
    int lane = threadIdx.x & 31;
    int e0 = off[d], e1 = off[d + 1];

    const float* qp = pack + 512;    // q block
    const float* kp = pack + 1024;   // k block
    const float* vp = pack + 1536;   // v block

    float4 qv = *((const float4*)(qp + (size_t)d * MPK + h * HID) + lane);
    float4 acc = make_float4(0.f, 0.f, 0.f, 0.f);
    float mrun = -CUDART_INF_F, den = 0.f;

    int i = e0;
    for (; i + 1 < e1; i += 2) {
        int s0 = srcs[i], s1 = srcs[i + 1];
        float4 k0 = *((const float4*)(kp + (size_t)s0 * MPK + h * HID) + lane);
        float4 k1 = *((const float4*)(kp + (size_t)s1 * MPK + h * HID) + lane);
        float d0 = qv.x * k0.x + qv.y * k0.y + qv.z * k0.z + qv.w * k0.w;
        float d1 = qv.x * k1.x + qv.y * k1.y + qv.z * k1.z + qv.w * k1.w;
#pragma unroll
        for (int o = 16; o; o >>= 1) {
            d0 += __shfl_xor_sync(0xffffffffu, d0, o);
            d1 += __shfl_xor_sync(0xffffffffu, d1, o);
        }
        d0 *= 0.08838834764831843f;
        d1 *= 0.08838834764831843f;
        float4 v0 = *((const float4*)(vp + (size_t)s0 * MPK + h * HID) + lane);
        float4 v1 = *((const float4*)(vp + (size_t)s1 * MPK + h * HID) + lane);

        float mnew = fmaxf(mrun, d0);
        float corr = __expf(mrun - mnew);
        float w    = __expf(d0 - mnew);
        den = den * corr + w;
        acc.x = acc.x * corr + w * v0.x;
        acc.y = acc.y * corr + w * v0.y;
        acc.z = acc.z * corr + w * v0.z;
        acc.w = acc.w * corr + w * v0.w;
        mrun = mnew;

        mnew = fmaxf(mrun, d1);
        corr = __expf(mrun - mnew);
        w    = __expf(d1 - mnew);
        den = den * corr + w;
        acc.x = acc.x * corr + w * v1.x;
        acc.y = acc.y * corr + w * v1.y;
        acc.z = acc.z * corr + w * v1.z;
        acc.w = acc.w * corr + w * v1.w;
        mrun = mnew;
    }
    if (i < e1) {
        int s0 = srcs[i];
        float4 k0 = *((const float4*)(kp + (size_t)s0 * MPK + h * HID) + lane);
        float d0 = qv.x * k0.x + qv.y * k0.y + qv.z * k0.z + qv.w * k0.w;
#pragma unroll
        for (int o = 16; o; o >>= 1) d0 += __shfl_xor_sync(0xffffffffu, d0, o);
        d0 *= 0.08838834764831843f;
        float4 v0 = *((const float4*)(vp + (size_t)s0 * MPK + h * HID) + lane);
        float mnew = fmaxf(mrun, d0);
        float corr = __expf(mrun - mnew);
        float w    = __expf(d0 - mnew);
        den = den * corr + w;
        acc.x = acc.x * corr + w * v0.x;
        acc.y = acc.y * corr + w * v0.y;
        acc.z = acc.z * corr + w * v0.z;
        acc.w = acc.w * corr + w * v0.w;
        mrun = mnew;
    }

    float inv = 1.f / (den + 1e-16f);
    // fused epilogue: + ts + skip, relu
    float4 ts = *((const float4*)(pack + 2048 + (size_t)d * MPK + h * HID) + lane);
    float4 sk = *((const float4*)(pack + 0    + (size_t)d * MPK + h * HID) + lane);
    float4 r;
    r.x = fmaxf(acc.x * inv + ts.x + sk.x, 0.f);
    r.y = fmaxf(acc.y * inv + ts.y + sk.y, 0.f);
    r.z = fmaxf(acc.z * inv + ts.z + sk.z, 0.f);
    r.w = fmaxf(acc.w * inv + ts.w + sk.w, 0.f);
    *((float4*)(h2 + (size_t)d * HC + h * HID) + lane) = r;
}

// ---------------------------------------------------------------------------
// Pooling + final FC
// ---------------------------------------------------------------------------
__global__ void pool_accum(const float* __restrict__ h,
                           const int* __restrict__ batch,
                           float* __restrict__ pool, float* __restrict__ cnt)
{
    int idx = blockIdx.x * blockDim.x + threadIdx.x;
    if (idx >= NN * HID) return;
    int i = idx >> 7, c = idx & 127;
    int b = batch[i];
    atomicAdd(&pool[b * HID + c], h[idx]);
    if (c == 0) atomicAdd(&cnt[b], 1.0f);
}

__global__ void pool_fc(const float* __restrict__ pool,
                        const float* __restrict__ cnt,
                        const float* __restrict__ fcW,
                        const float* __restrict__ fcb,
                        float* __restrict__ out)
{
    int g = blockIdx.x;
    int c = threadIdx.x;
    float inv = 1.f / fmaxf(cnt[g], 1.f);
    float s = 0.f;
    for (int k = 0; k < HID; k++)
        s += pool[g * HID + k] * fcW[k * NCC + c];
    out[g * NCC + c] = s * inv + fcb[c];
}

// ---------------------------------------------------------------------------
// Launch
// ---------------------------------------------------------------------------
extern "C" void kernel_launch(void* const* d_in, const int* in_sizes, int n_in,
                              void* d_out, int out_size)
{
    const float* x        = (const float*)d_in[0];
    const int*   ei       = (const int*)  d_in[1];
    const int*   src      = ei;
    const int*   dst      = ei + EE;
    const int*   batch    = (const int*)  d_in[2];
    const float* c1_Wr    = (const float*)d_in[3];
    const float* c1_br    = (const float*)d_in[4];
    const float* c1_Wroot = (const float*)d_in[5];
    const float* tq_W  = (const float*)d_in[6];  const float* tq_b  = (const float*)d_in[7];
    const float* tk_W  = (const float*)d_in[8];  const float* tk_b  = (const float*)d_in[9];
    const float* tv_W  = (const float*)d_in[10]; const float* tv_b  = (const float*)d_in[11];
    const float* ts_W  = (const float*)d_in[12]; const float* ts_b  = (const float*)d_in[13];
    const float* skip_W = (const float*)d_in[14];
    const float* l1W    = (const float*)d_in[15]; const float* l1b = (const float*)d_in[16];
    const float* g1_Wr = (const float*)d_in[17]; const float* g1_br = (const float*)d_in[18];
    const float* g1_Wroot = (const float*)d_in[19];
    const float* g2_Wr = (const float*)d_in[20]; const float* g2_br = (const float*)d_in[21];
    const float* g2_Wroot = (const float*)d_in[22];
    const float* fc_W = (const float*)d_in[23]; const float* fc_b = (const float*)d_in[24];
    float* out = (float*)d_out;

    float *agg, *h, *h3, *h4, *h5, *pack, *h2, *Wpk, *bpk, *pool, *cnt;
    int *deg, *cur, *off, *srcs;
    cudaGetSymbolAddress((void**)&agg,  g_agg);
    cudaGetSymbolAddress((void**)&h,    g_h);
    cudaGetSymbolAddress((void**)&h3,   g_h3);
    cudaGetSymbolAddress((void**)&h4,   g_h4);
    cudaGetSymbolAddress((void**)&h5,   g_h5);
    cudaGetSymbolAddress((void**)&pack, g_pack);
    cudaGetSymbolAddress((void**)&h2,   g_h2);
    cudaGetSymbolAddress((void**)&Wpk,  g_Wpk);
    cudaGetSymbolAddress((void**)&bpk,  g_bpk);
    cudaGetSymbolAddress((void**)&pool, g_pool);
    cudaGetSymbolAddress((void**)&cnt,  g_cnt);
    cudaGetSymbolAddress((void**)&deg,  g_deg);
    cudaGetSymbolAddress((void**)&cur,  g_cur);
    cudaGetSymbolAddress((void**)&off,  g_off);
    cudaGetSymbolAddress((void**)&srcs, g_srcs);

    const dim3 gb(256);
    const dim3 grid128((NN + 127) / 128, 2);    // Mout = 128
    const dim3 gridPK ((NN + 127) / 128, MPK / 64);

    // --- weight packing (independent of everything else)
    pack_weights<<<(HID * MPK / 4 + 255) / 256, 256>>>(skip_W, tq_W, tk_W, tv_W,
                                                       ts_W, Wpk);
    pack_bias<<<(MPK + 255) / 256, 256>>>(tq_b, tk_b, tv_b, ts_b, bpk);

    // --- CSR build (by dst)
    cudaMemsetAsync(deg, 0, NN * sizeof(int));
    deg_count<<<(EE + 255) / 256, 256>>>(dst, deg);
    scan_offsets<<<1, 1024>>>(deg, off, cur);
    build_srcs<<<(EE + 255) / 256, 256>>>(src, dst, cur, srcs);

    // --- conv1: h = relu( (agg x) @ Wr + br + x @ Wroot )
    gconv_agg<<<NN, 128>>>(x, off, srcs, agg);
    gemm_mma<<<grid128, gb>>>(agg, c1_Wr, x, c1_Wroot, c1_br,
                              nullptr, h, NN, 128, 128, 1);

    // --- packed projections: [skip | q | k | v | ts] = h @ Wpk + bpk
    gemm_mma<<<gridPK, gb>>>(h, Wpk, nullptr, nullptr, bpk,
                             nullptr, pack, NN, 128, MPK, 0);

    // --- attention + fused epilogue: h2 = relu(attn + ts + skip)
    attn_fused<<<NN, 128>>>(pack, off, srcs, h2);

    // --- h3 = relu(h2 @ lin1_W + lin1_b)
    gemm_mma<<<grid128, gb>>>(h2, l1W, nullptr, nullptr, l1b,
                              nullptr, h3, NN, 512, 128, 1);

    // --- gconv l1 with residual
    gconv_agg<<<NN, 128>>>(h3, off, srcs, agg);
    gemm_mma<<<grid128, gb>>>(agg, g1_Wr, h3, g1_Wroot, g1_br,
                              h3, h4, NN, 128, 128, 1);

    // --- gconv l2 with residual
    gconv_agg<<<NN, 128>>>(h4, off, srcs, agg);
    gemm_mma<<<grid128, gb>>>(agg, g2_Wr, h4, g2_Wroot, g2_br,
                              h4, h5, NN, 128, 128, 1);

    // --- mean pool + fc
    cudaMemsetAsync(pool, 0, (size_t)GG * HID * sizeof(float));
    cudaMemsetAsync(cnt,  0, (size_t)GG * sizeof(float));
    pool_accum<<<(NN * HID + 255) / 256, 256>>>(h5, batch, pool, cnt);
    pool_fc<<<GG, NCC>>>(pool, cnt, fc_W, fc_b, out);
}

// round 7
// speedup vs baseline: 2.0498x; 1.0354x over previous
#include <cuda_runtime.h>
#include <cuda_bf16.h>
#include <cstdint>

// Problem constants (fixed by the dataset)
#define NN   20000
#define EE   160000
#define HID  128
#define NHEADS 4
#define GG   64
#define NCC  8
#define HC   512
#define MPK  2560      // packed projection width: [skip | q | k | v | ts]
#define NEGBIG (-1.0e30f)

// ---------------------------------------------------------------------------
// Scratch (device globals: allocation-free contract)
// ---------------------------------------------------------------------------
__device__ float g_agg [NN * HID];
__device__ float g_h   [NN * HID];
__device__ float g_h3  [NN * HID];
__device__ float g_h4  [NN * HID];
__device__ float g_h5  [NN * HID];
__device__ float g_pack[(size_t)NN * MPK];
__device__ float g_h2  [NN * HC];
__device__ float g_Wpk [HID * MPK];
__device__ float g_bpk [MPK];
__device__ float g_pool[GG * HID];
__device__ float g_cnt [GG];
// CSR (by dst)
__device__ int   g_deg [NN];
__device__ int   g_cur [NN];
__device__ int   g_off [NN + 1];
__device__ int   g_srcs[EE];

// ---------------------------------------------------------------------------
// mma.sync bf16 GEMM with 3xBF16 split + register-prefetch pipeline
// C[Nrows, Mtot] = op( A@W [+ A2@W2] [+bias] [+add1] ), W: [K, Mtot]
// CTA tile 128x64, BK=32. 8 warps (2m x 4n), warp tile 64x16, 2 CTAs/SM.
// ---------------------------------------------------------------------------
#define A_HI 0
#define A_LO 10240
#define B_HI 20480
#define B_LO 25600
#define SSTR 80

__device__ __forceinline__ unsigned pack_hi(float x, float y) {
    __nv_bfloat162 p;
    p.x = __float2bfloat16_rn(x);
    p.y = __float2bfloat16_rn(y);
    return *(unsigned*)&p;
}
__device__ __forceinline__ unsigned pack_lo(float x, float y) {
    __nv_bfloat162 p;
    p.x = __float2bfloat16_rn(x - __bfloat162float(__float2bfloat16_rn(x)));
    p.y = __float2bfloat16_rn(y - __bfloat162float(__float2bfloat16_rn(y)));
    return *(unsigned*)&p;
}

__device__ __forceinline__ void mma_bf16(float* c, const unsigned* a, const unsigned* b) {
    asm volatile(
        "mma.sync.aligned.m16n8k16.row.col.f32.bf16.bf16.f32 "
        "{%0,%1,%2,%3}, {%4,%5,%6,%7}, {%8,%9}, {%0,%1,%2,%3};"
        : "+f"(c[0]), "+f"(c[1]), "+f"(c[2]), "+f"(c[3])
        : "r"(a[0]), "r"(a[1]), "r"(a[2]), "r"(a[3]), "r"(b[0]), "r"(b[1]));
}

__device__ __forceinline__ void load_tiles(const float* __restrict__ Ap,
                                           const float* __restrict__ Wp,
                                           int K, int Mtot, int Nrows,
                                           int brow, int bcol, int k0, int tid,
                                           float4 pa[4], float4 pb[2])
{
#pragma unroll
    for (int t = 0; t < 4; ++t) {
        int idx = tid + t * 256;
        int r   = idx >> 3;
        int kg  = idx & 7;
        pa[t] = make_float4(0.f, 0.f, 0.f, 0.f);
        if (brow + r < Nrows)
            pa[t] = *(const float4*)(Ap + (size_t)(brow + r) * K + k0 + kg * 4);
    }
#pragma unroll
    for (int t = 0; t < 2; ++t) {
        int idx = tid + t * 256;
        int n   = idx & 63;
        int kg  = idx >> 6;
        const float* wp = Wp + (size_t)(k0 + kg * 4) * Mtot + bcol + n;
        pb[t] = make_float4(wp[0], wp[Mtot], wp[2 * (size_t)Mtot],
                            wp[3 * (size_t)Mtot]);
    }
}

__global__ void __launch_bounds__(256, 2)
gemm_mma(const float* __restrict__ A,  const float* __restrict__ W,
         const float* __restrict__ A2, const float* __restrict__ W2,
         const float* __restrict__ bias,
         const float* __restrict__ add1,
         float* __restrict__ C, int Nrows, int K, int Mtot, int do_relu)
{
    __shared__ __align__(16) char smem[30720];

    const int tid    = threadIdx.x;
    const int wid    = tid >> 5;
    const int lane   = tid & 31;
    const int warp_m = wid >> 2;
    const int warp_n = wid & 3;
    const int g      = lane >> 2;
    const int t4     = (lane & 3) * 4;
    const int brow   = blockIdx.x * 128;
    const int bcol   = blockIdx.y * 64;

    float acc[4][2][4];
#pragma unroll
    for (int i = 0; i < 4; i++)
#pragma unroll
        for (int j = 0; j < 2; j++)
#pragma unroll
            for (int r = 0; r < 4; r++) acc[i][j][r] = 0.f;

    const int kch = K >> 5;
    const int nch = A2 ? kch * 2 : kch;

    float4 pa[4], pb[2];
    load_tiles(A, W, K, Mtot, Nrows, brow, bcol, 0, tid, pa, pb);

    for (int c = 0; c < nch; ++c) {
        __syncthreads();   // previous compute done; smem free

        // ---- store prefetched regs -> smem (convert to bf16 hi/lo)
#pragma unroll
        for (int t = 0; t < 4; ++t) {
            int idx = tid + t * 256;
            int r   = idx >> 3;
            int kg  = idx & 7;
            int off = r * SSTR + kg * 8;
            *(uint2*)(smem + A_HI + off) =
                make_uint2(pack_hi(pa[t].x, pa[t].y), pack_hi(pa[t].z, pa[t].w));
            *(uint2*)(smem + A_LO + off) =
                make_uint2(pack_lo(pa[t].x, pa[t].y), pack_lo(pa[t].z, pa[t].w));
        }
#pragma unroll
        for (int t = 0; t < 2; ++t) {
            int idx = tid + t * 256;
            int n   = idx & 63;
            int kg  = idx >> 6;
            int off = n * SSTR + kg * 8;
            *(uint2*)(smem + B_HI + off) =
                make_uint2(pack_hi(pb[t].x, pb[t].y), pack_hi(pb[t].z, pb[t].w));
            *(uint2*)(smem + B_LO + off) =
                make_uint2(pack_lo(pb[t].x, pb[t].y), pack_lo(pb[t].z, pb[t].w));
        }

        // ---- issue next chunk's global loads (overlap with MMA below)
        if (c + 1 < nch) {
            int cn   = c + 1;
            int pass = cn / kch;
            int k0   = (cn % kch) * 32;
            load_tiles(pass ? A2 : A, pass ? W2 : W, K, Mtot, Nrows,
                       brow, bcol, k0, tid, pa, pb);
        }
        __syncthreads();   // smem tiles ready

        // ---- compute: 2 k-steps of 16
#pragma unroll
        for (int ks = 0; ks < 2; ++ks) {
            const int ko = ks * 32;
            unsigned aH[4][4], aL[4][4], bH[2][2], bL[2][2];
#pragma unroll
            for (int nt = 0; nt < 2; ++nt) {
                int nb = (warp_n * 16 + nt * 8 + g) * SSTR + t4 + ko;
                bH[nt][0] = *(const unsigned*)(smem + B_HI + nb);
                bH[nt][1] = *(const unsigned*)(smem + B_HI + nb + 16);
                bL[nt][0] = *(const unsigned*)(smem + B_LO + nb);
                bL[nt][1] = *(const unsigned*)(smem + B_LO + nb + 16);
            }
#pragma unroll
            for (int mt = 0; mt < 4; ++mt) {
                int mb = (warp_m * 64 + mt * 16 + g) * SSTR + t4 + ko;
                aH[mt][0] = *(const unsigned*)(smem + A_HI + mb);
                aH[mt][1] = *(const unsigned*)(smem + A_HI + mb + 8 * SSTR);
                aH[mt][2] = *(const unsigned*)(smem + A_HI + mb + 16);
                aH[mt][3] = *(const unsigned*)(smem + A_HI + mb + 8 * SSTR + 16);
                aL[mt][0] = *(const unsigned*)(smem + A_LO + mb);
                aL[mt][1] = *(const unsigned*)(smem + A_LO + mb + 8 * SSTR);
                aL[mt][2] = *(const unsigned*)(smem + A_LO + mb + 16);
                aL[mt][3] = *(const unsigned*)(smem + A_LO + mb + 8 * SSTR + 16);
            }
#pragma unroll
            for (int mt = 0; mt < 4; ++mt)
#pragma unroll
                for (int nt = 0; nt < 2; ++nt) {
                    mma_bf16(acc[mt][nt], aH[mt], bH[nt]);
                    mma_bf16(acc[mt][nt], aH[mt], bL[nt]);
                    mma_bf16(acc[mt][nt], aL[mt], bH[nt]);
                }
        }
    }

    // ---- epilogue
#pragma unroll
    for (int mt = 0; mt < 4; ++mt) {
#pragma unroll
        for (int nt = 0; nt < 2; ++nt) {
            int col = bcol + warp_n * 16 + nt * 8 + (lane & 3) * 2;
#pragma unroll
            for (int half = 0; half < 2; ++half) {
                int row = brow + warp_m * 64 + mt * 16 + g + half * 8;
                if (row >= Nrows) continue;
                float v0 = acc[mt][nt][half * 2 + 0];
                float v1 = acc[mt][nt][half * 2 + 1];
                if (bias) {
                    float2 b = *(const float2*)(bias + col);
                    v0 += b.x; v1 += b.y;
                }
                size_t o = (size_t)row * Mtot + col;
                if (add1) {
                    float2 a = *(const float2*)(add1 + o);
                    v0 += a.x; v1 += a.y;
                }
                if (do_relu) { v0 = fmaxf(v0, 0.f); v1 = fmaxf(v1, 0.f); }
                *(float2*)(C + o) = make_float2(v0, v1);
            }
        }
    }
}

// ---------------------------------------------------------------------------
// Weight/bias packing
// ---------------------------------------------------------------------------
__global__ void pack_weights(const float* __restrict__ w0,
                             const float* __restrict__ w1,
                             const float* __restrict__ w2,
                             const float* __restrict__ w3,
                             const float* __restrict__ w4,
                             float* __restrict__ Wp)
{
    int idx = blockIdx.x * blockDim.x + threadIdx.x;
    if (idx >= HID * MPK / 4) return;
    int row = idx / (MPK / 4);
    int col = (idx % (MPK / 4)) * 4;
    int b   = col >> 9;
    int c   = col & 511;
    const float* srcs[5] = {w0, w1, w2, w3, w4};
    *(float4*)(Wp + (size_t)row * MPK + col) =
        *(const float4*)(srcs[b] + (size_t)row * HC + c);
}

__global__ void pack_bias(const float* __restrict__ b1, const float* __restrict__ b2,
                          const float* __restrict__ b3, const float* __restrict__ b4,
                          float* __restrict__ bp)
{
    int col = blockIdx.x * blockDim.x + threadIdx.x;
    if (col >= MPK) return;
    int b = col >> 9, c = col & 511;
    float v = 0.f;
    if (b == 1) v = b1[c];
    else if (b == 2) v = b2[c];
    else if (b == 3) v = b3[c];
    else if (b == 4) v = b4[c];
    bp[col] = v;
}

// ---------------------------------------------------------------------------
// CSR build (by dst)
// ---------------------------------------------------------------------------
__global__ void deg_count(const int* __restrict__ dst, int* __restrict__ deg)
{
    int e = blockIdx.x * blockDim.x + threadIdx.x;
    if (e < EE) atomicAdd(&deg[dst[e]], 1);
}

// 1024 threads, warp-shuffle scan: 2 barriers total
__global__ void scan_offsets(const int* __restrict__ deg,
                             int* __restrict__ off, int* __restrict__ cur)
{
    __shared__ int wsum[32];
    const int t    = threadIdx.x;
    const int lane = t & 31;
    const int wid  = t >> 5;
    const int CH   = (NN + 1023) / 1024;   // 20

    int local[CH];
    int s = 0;
    int base = t * CH;
#pragma unroll
    for (int i = 0; i < CH; i++) {
        int idx = base + i;
        local[i] = (idx < NN) ? deg[idx] : 0;
        s += local[i];
    }
    // warp inclusive scan of s
    int v = s;
#pragma unroll
    for (int o = 1; o < 32; o <<= 1) {
        int u = __shfl_up_sync(0xffffffffu, v, o);
        if (lane >= o) v += u;
    }
    if (lane == 31) wsum[wid] = v;
    __syncthreads();
    if (wid == 0) {
        int w = wsum[lane];
#pragma unroll
        for (int o = 1; o < 32; o <<= 1) {
            int u = __shfl_up_sync(0xffffffffu, w, o);
            if (lane >= o) w += u;
        }
        wsum[lane] = w;
    }
    __syncthreads();
    int excl = v - s + (wid ? wsum[wid - 1] : 0);
#pragma unroll
    for (int i = 0; i < CH; i++) {
        int idx = base + i;
        if (idx < NN) {
            off[idx] = excl;
            cur[idx] = excl;
            excl += local[i];
        }
    }
    if (t == 1023) off[NN] = excl;
}

__global__ void build_srcs(const int* __restrict__ src, const int* __restrict__ dst,
                           int* __restrict__ cur, int* __restrict__ srcs)
{
    int e = blockIdx.x * blockDim.x + threadIdx.x;
    if (e >= EE) return;
    int pos = atomicAdd(&cur[dst[e]], 1);
    srcs[pos] = src[e];
}

// ---------------------------------------------------------------------------
// GraphConv aggregation via CSR
// ---------------------------------------------------------------------------
__global__ void gconv_agg(const float* __restrict__ in,
                          const int* __restrict__ off,
                          const int* __restrict__ srcs,
                          float* __restrict__ agg)
{
    int d = blockIdx.x;
    int c = threadIdx.x;
    int e0 = off[d], e1 = off[d + 1];
    float s = 0.f;
    int i = e0;
    for (; i + 3 < e1; i += 4) {
        int s0 = srcs[i], s1 = srcs[i + 1], s2 = srcs[i + 2], s3 = srcs[i + 3];
        s += in[(size_t)s0 * HID + c] + in[(size_t)s1 * HID + c]
           + in[(size_t)s2 * HID + c] + in[(size_t)s3 * HID + c];
    }
    for (; i < e1; ++i)
        s += in[(size_t)srcs[i] * HID + c];
    agg[(size_t)d * HID + c] = s;
}

// ---------------------------------------------------------------------------
// Attention + transformer epilogue fused, 8 warps/node (2 warps per head):
//   h2[d] = relu( softmax-attn(d) + ts[d] + skip[d] )
// Online softmax with finite sentinel; partial states merged via smem.
// ---------------------------------------------------------------------------
__global__ void __launch_bounds__(256)
attn_fused(const float* __restrict__ pack,
           const int* __restrict__ off,
           const int* __restrict__ srcs,
           float* __restrict__ h2)
{
    __shared__ float s_m[4], s_den[4], s_acc[4][128];

    int d    = blockIdx.x;
    int w    = threadIdx.x >> 5;
    int lane = threadIdx.x & 31;
    int h    = w & 3;
    int half = w >> 2;
    int e0 = off[d], e1 = off[d + 1];
    int emid = (e0 + e1) >> 1;
    int lo = half ? emid : e0;
    int hi = half ? e1   : emid;

    const float* qp = pack + 512;
    const float* kp = pack + 1024;
    const float* vp = pack + 1536;

    float4 qv = *((const float4*)(qp + (size_t)d * MPK + h * HID) + lane);
    float4 acc = make_float4(0.f, 0.f, 0.f, 0.f);
    float mrun = NEGBIG, den = 0.f;

    int i = lo;
    for (; i + 1 < hi; i += 2) {
        int s0 = srcs[i], s1 = srcs[i + 1];
        float4 k0 = *((const float4*)(kp + (size_t)s0 * MPK + h * HID) + lane);
        float4 k1 = *((const float4*)(kp + (size_t)s1 * MPK + h * HID) + lane);
        float4 v0 = *((const float4*)(vp + (size_t)s0 * MPK + h * HID) + lane);
        float4 v1 = *((const float4*)(vp + (size_t)s1 * MPK + h * HID) + lane);
        float d0 = qv.x * k0.x + qv.y * k0.y + qv.z * k0.z + qv.w * k0.w;
        float d1 = qv.x * k1.x + qv.y * k1.y + qv.z * k1.z + qv.w * k1.w;
#pragma unroll
        for (int o = 16; o; o >>= 1) {
            d0 += __shfl_xor_sync(0xffffffffu, d0, o);
            d1 += __shfl_xor_sync(0xffffffffu, d1, o);
        }
        d0 *= 0.08838834764831843f;
        d1 *= 0.08838834764831843f;

        float mnew = fmaxf(mrun, d0);
        float corr = __expf(mrun - mnew);
        float wt   = __expf(d0 - mnew);
        den = den * corr + wt;
        acc.x = acc.x * corr + wt * v0.x;
        acc.y = acc.y * corr + wt * v0.y;
        acc.z = acc.z * corr + wt * v0.z;
        acc.w = acc.w * corr + wt * v0.w;
        mrun = mnew;

        mnew = fmaxf(mrun, d1);
        corr = __expf(mrun - mnew);
        wt   = __expf(d1 - mnew);
        den = den * corr + wt;
        acc.x = acc.x * corr + wt * v1.x;
        acc.y = acc.y * corr + wt * v1.y;
        acc.z = acc.z * corr + wt * v1.z;
        acc.w = acc.w * corr + wt * v1.w;
        mrun = mnew;
    }
    if (i < hi) {
        int s0 = srcs[i];
        float4 k0 = *((const float4*)(kp + (size_t)s0 * MPK + h * HID) + lane);
        float4 v0 = *((const float4*)(vp + (size_t)s0 * MPK + h * HID) + lane);
        float d0 = qv.x * k0.x + qv.y * k0.y + qv.z * k0.z + qv.w * k0.w;
#pragma unroll
        for (int o = 16; o; o >>= 1) d0 += __shfl_xor_sync(0xffffffffu, d0, o);
        d0 *= 0.08838834764831843f;
        float mnew = fmaxf(mrun, d0);
        float corr = __expf(mrun - mnew);
        float wt   = __expf(d0 - mnew);
        den = den * corr + wt;
        acc.x = acc.x * corr + wt * v0.x;
        acc.y = acc.y * corr + wt * v0.y;
        acc.z = acc.z * corr + wt * v0.z;
        acc.w = acc.w * corr + wt * v0.w;
        mrun = mnew;
    }

    // merge upper-half warp state into lower-half warp
    if (half == 1) {
        if (lane == 0) { s_m[h] = mrun; s_den[h] = den; }
        *((float4*)&s_acc[h][0] + lane) = acc;
    }
    __syncthreads();
    if (half == 0) {
        float m1 = s_m[h], den1 = s_den[h];
        float4 a1 = *((const float4*)&s_acc[h][0] + lane);
        float mnew = fmaxf(mrun, m1);
        float c0 = __expf(mrun - mnew);
        float c1 = __expf(m1 - mnew);
        den = den * c0 + den1 * c1;
        acc.x = acc.x * c0 + a1.x * c1;
        acc.y = acc.y * c0 + a1.y * c1;
        acc.z = acc.z * c0 + a1.z * c1;
        acc.w = acc.w * c0 + a1.w * c1;

        float inv = 1.f / (den + 1e-16f);
        float4 ts = *((const float4*)(pack + 2048 + (size_t)d * MPK + h * HID) + lane);
        float4 sk = *((const float4*)(pack + 0    + (size_t)d * MPK + h * HID) + lane);
        float4 r;
        r.x = fmaxf(acc.x * inv + ts.x + sk.x, 0.f);
        r.y = fmaxf(acc.y * inv + ts.y + sk.y, 0.f);
        r.z = fmaxf(acc.z * inv + ts.z + sk.z, 0.f);
        r.w = fmaxf(acc.w * inv + ts.w + sk.w, 0.f);
        *((float4*)(h2 + (size_t)d * HC + h * HID) + lane) = r;
    }
}

// ---------------------------------------------------------------------------
// Pooling (batch sorted: accumulate runs, flush atomics on group change)
// ---------------------------------------------------------------------------
#define PB 64
__global__ void pool_accum(const float* __restrict__ h,
                           const int* __restrict__ batch,
                           float* __restrict__ pool, float* __restrict__ cnt)
{
    int c  = threadIdx.x;     // 0..127
    int n0 = blockIdx.x * PB;
    int n1 = min(n0 + PB, NN);
    float s = 0.f;
    int cb = batch[n0], count = 0;
    for (int n = n0; n < n1; ++n) {
        int b = batch[n];
        if (b != cb) {
            atomicAdd(&pool[cb * HID + c], s);
            if (c == 0) atomicAdd(&cnt[cb], (float)count);
            s = 0.f; count = 0; cb = b;
        }
        s += h[(size_t)n * HID + c];
        count++;
    }
    atomicAdd(&pool[cb * HID + c], s);
    if (c == 0) atomicAdd(&cnt[cb], (float)count);
}

__global__ void pool_fc(const float* __restrict__ pool,
                        const float* __restrict__ cnt,
                        const float* __restrict__ fcW,
                        const float* __restrict__ fcb,
                        float* __restrict__ out)
{
    int g = blockIdx.x;
    int c = threadIdx.x;
    float inv = 1.f / fmaxf(cnt[g], 1.f);
    float s = 0.f;
    for (int k = 0; k < HID; k++)
        s += pool[g * HID + k] * fcW[k * NCC + c];
    out[g * NCC + c] = s * inv + fcb[c];
}

// ---------------------------------------------------------------------------
// Launch
// ---------------------------------------------------------------------------
extern "C" void kernel_launch(void* const* d_in, const int* in_sizes, int n_in,
                              void* d_out, int out_size)
{
    const float* x        = (const float*)d_in[0];
    const int*   ei       = (const int*)  d_in[1];
    const int*   src      = ei;
    const int*   dst      = ei + EE;
    const int*   batch    = (const int*)  d_in[2];
    const float* c1_Wr    = (const float*)d_in[3];
    const float* c1_br    = (const float*)d_in[4];
    const float* c1_Wroot = (const float*)d_in[5];
    const float* tq_W  = (const float*)d_in[6];  const float* tq_b  = (const float*)d_in[7];
    const float* tk_W  = (const float*)d_in[8];  const float* tk_b  = (const float*)d_in[9];
    const float* tv_W  = (const float*)d_in[10]; const float* tv_b  = (const float*)d_in[11];
    const float* ts_W  = (const float*)d_in[12]; const float* ts_b  = (const float*)d_in[13];
    const float* skip_W = (const float*)d_in[14];
    const float* l1W    = (const float*)d_in[15]; const float* l1b = (const float*)d_in[16];
    const float* g1_Wr = (const float*)d_in[17]; const float* g1_br = (const float*)d_in[18];
    const float* g1_Wroot = (const float*)d_in[19];
    const float* g2_Wr = (const float*)d_in[20]; const float* g2_br = (const float*)d_in[21];
    const float* g2_Wroot = (const float*)d_in[22];
    const float* fc_W = (const float*)d_in[23]; const float* fc_b = (const float*)d_in[24];
    float* out = (float*)d_out;

    float *agg, *h, *h3, *h4, *h5, *pack, *h2, *Wpk, *bpk, *pool, *cnt;
    int *deg, *cur, *off, *srcs;
    cudaGetSymbolAddress((void**)&agg,  g_agg);
    cudaGetSymbolAddress((void**)&h,    g_h);
    cudaGetSymbolAddress((void**)&h3,   g_h3);
    cudaGetSymbolAddress((void**)&h4,   g_h4);
    cudaGetSymbolAddress((void**)&h5,   g_h5);
    cudaGetSymbolAddress((void**)&pack, g_pack);
    cudaGetSymbolAddress((void**)&h2,   g_h2);
    cudaGetSymbolAddress((void**)&Wpk,  g_Wpk);
    cudaGetSymbolAddress((void**)&bpk,  g_bpk);
    cudaGetSymbolAddress((void**)&pool, g_pool);
    cudaGetSymbolAddress((void**)&cnt,  g_cnt);
    cudaGetSymbolAddress((void**)&deg,  g_deg);
    cudaGetSymbolAddress((void**)&cur,  g_cur);
    cudaGetSymbolAddress((void**)&off,  g_off);
    cudaGetSymbolAddress((void**)&srcs, g_srcs);

    const dim3 gb(256);
    const dim3 grid128((NN + 127) / 128, 2);
    const dim3 gridPK ((NN + 127) / 128, MPK / 64);

    // --- weight packing (independent)
    pack_weights<<<(HID * MPK / 4 + 255) / 256, 256>>>(skip_W, tq_W, tk_W, tv_W,
                                                       ts_W, Wpk);
    pack_bias<<<(MPK + 255) / 256, 256>>>(tq_b, tk_b, tv_b, ts_b, bpk);

    // --- CSR build (by dst)
    cudaMemsetAsync(deg, 0, NN * sizeof(int));
    deg_count<<<(EE + 255) / 256, 256>>>(dst, deg);
    scan_offsets<<<1, 1024>>>(deg, off, cur);
    build_srcs<<<(EE + 255) / 256, 256>>>(src, dst, cur, srcs);

    // --- conv1: h = relu( (agg x) @ Wr + br + x @ Wroot )
    gconv_agg<<<NN, 128>>>(x, off, srcs, agg);
    gemm_mma<<<grid128, gb>>>(agg, c1_Wr, x, c1_Wroot, c1_br,
                              nullptr, h, NN, 128, 128, 1);

    // --- packed projections: [skip | q | k | v | ts] = h @ Wpk + bpk
    gemm_mma<<<gridPK, gb>>>(h, Wpk, nullptr, nullptr, bpk,
                             nullptr, pack, NN, 128, MPK, 0);

    // --- attention + fused epilogue
    attn_fused<<<NN, 256>>>(pack, off, srcs, h2);

    // --- h3 = relu(h2 @ lin1_W + lin1_b)
    gemm_mma<<<grid128, gb>>>(h2, l1W, nullptr, nullptr, l1b,
                              nullptr, h3, NN, 512, 128, 1);

    // --- gconv l1 with residual
    gconv_agg<<<NN, 128>>>(h3, off, srcs, agg);
    gemm_mma<<<grid128, gb>>>(agg, g1_Wr, h3, g1_Wroot, g1_br,
                              h3, h4, NN, 128, 128, 1);

    // --- gconv l2 with residual
    gconv_agg<<<NN, 128>>>(h4, off, srcs, agg);
    gemm_mma<<<grid128, gb>>>(agg, g2_Wr, h4, g2_Wroot, g2_br,
                              h4, h5, NN, 128, 128, 1);

    // --- mean pool + fc
    cudaMemsetAsync(pool, 0, (size_t)GG * HID * sizeof(float));
    cudaMemsetAsync(cnt,  0, (size_t)GG * sizeof(float));
    pool_accum<<<(NN + PB - 1) / PB, 128>>>(h5, batch, pool, cnt);
    pool_fc<<<GG, NCC>>>(pool, cnt, fc_W, fc_b, out);
}